// round 12
// baseline (speedup 1.0000x reference)
#include <cuda_runtime.h>
#include <cuda_bf16.h>
#include <cuda_fp16.h>
#include <math.h>

// z [8192,256] f32, embedding [4096,256] f32.
// out = [ sigmoid(z z^T) (8192x8192 f32) , argmax cosine indices (8192 f32) ]
// adj: fp16 asymmetric 2-term (Ah+Al)x(Bh) mma.sync, FMA sigmoid, sym tiles.
// cos: bf16 1-term mma.sync, FUSED candidate capture (running row max +
//      margin band) -> tiny per-row candidate lists; NO cosine matrix.
// rescore: exact sequential-fmaf dots of ~3 candidates/row (order matches
//      reference; proven R6), parallel over candidates.
// NOTE: tcgen05 unavailable (harness targets compute_103 without 'a').

#define KDIM 256
#define TILE 128
#define NMAX 8192
#define VMAX 4096
#define NSPLIT 8
#define AST  40          // smem row stride in elements (80B rows)
#define SST  132         // mirror-staging row stride in f32
#define MARGIN 1.0e-2f   // > 2.5x the 3.9e-3 worst-case 1-term bf16 dot error
#define CAP  64          // per-row global candidate cap
#define BCAP 1024        // per-block smem candidate cap
#define BUFB (TILE * AST * 2)   // 10240 bytes per operand buffer

__device__ __half g_zh [NMAX * KDIM];
__device__ __half g_zl [NMAX * KDIM];
__device__ __nv_bfloat16 g_znh[NMAX * KDIM];
__device__ __nv_bfloat16 g_enh[VMAX * KDIM];
__device__ float g_znf[NMAX * KDIM];
__device__ float g_enf[VMAX * KDIM];
__device__ int   g_ccnt[NMAX];
__device__ int   g_ccol[NMAX][CAP];
__device__ float g_cval[NMAX][CAP];

// ---------------- order-preserving float <-> uint ---------------------------
__device__ __forceinline__ unsigned fenc(float f) {
    unsigned b = __float_as_uint(f);
    return (b & 0x80000000u) ? ~b : (b | 0x80000000u);
}
__device__ __forceinline__ float fdec(unsigned u) {
    return (u & 0x80000000u) ? __uint_as_float(u & 0x7FFFFFFFu)
                             : __uint_as_float(~u);
}

// ---------------- cp.async helpers ------------------------------------------
#define CP16(sa, gp) \
    asm volatile("cp.async.cg.shared.global [%0], [%1], 16;" \
                 :: "r"(sa), "l"(gp) : "memory")
#define CP_COMMIT() asm volatile("cp.async.commit_group;" ::: "memory")
#define CP_WAIT0()  asm volatile("cp.async.wait_group 0;" ::: "memory")

// ===================== FMA-only sigmoid (no MUFU) ===========================
__device__ __forceinline__ float sigmoid_fast(float x) {
    float ax = fminf(fabsf(x), 30.0f);
    float u  = ax * 1.4426950408889634f;
    float fm = u + 12582912.0f;
    float n  = fm - 12582912.0f;
    float f  = n - u;
    float p  = 1.3333558146428443e-3f;
    p = fmaf(p, f, 9.6181291976353954e-3f);
    p = fmaf(p, f, 5.5504108664798463e-2f);
    p = fmaf(p, f, 2.4022650695910071e-1f);
    p = fmaf(p, f, 6.9314718055994531e-1f);
    p = fmaf(p, f, 1.0f);
    int nbits = (__float_as_int(fm) & 0x7F) << 23;
    float scale = __int_as_float(0x3F800000 - nbits);
    float q = p * scale;
    float d = 1.0f + q;
    float r = fmaf(d, fmaf(d, 0.33333333f, -1.5f), 2.16666667f);
    r = r * (2.0f - d * r);
    r = r * (2.0f - d * r);
    return (x >= 0.0f) ? r : r * q;
}

// ===================== prep: normalize + splits =============================
__global__ void prep_kernel(const float* __restrict__ z,
                            const float* __restrict__ e,
                            int N, int V) {
    int row = blockIdx.x;
    int tid = threadIdx.x;
    bool isZ = row < N;
    const float* src = isZ ? (z + (size_t)row * KDIM)
                           : (e + (size_t)(row - N) * KDIM);
    float v = src[tid];

    float ss = v * v;
    #pragma unroll
    for (int o = 16; o; o >>= 1) ss += __shfl_xor_sync(0xffffffffu, ss, o);
    __shared__ float s_partial[8];
    __shared__ float s_total;
    if ((tid & 31) == 0) s_partial[tid >> 5] = ss;
    __syncthreads();
    if (tid == 0) {
        float t = 0.f;
        #pragma unroll
        for (int i = 0; i < 8; i++) t += s_partial[i];
        s_total = t;
    }
    __syncthreads();
    float inv = 1.0f / fmaxf(sqrtf(s_total), 1e-8f);
    float vn = v * inv;

    if (isZ) {
        size_t o = (size_t)row * KDIM + tid;
        __half h = __float2half_rn(v);
        g_zh[o] = h;
        g_zl[o] = __float2half_rn(v - __half2float(h));
        g_znh[o] = __float2bfloat16(vn);
        g_znf[o] = vn;
        if (tid == 0) g_ccnt[row] = 0;
    } else {
        size_t o = (size_t)(row - N) * KDIM + tid;
        g_enh[o] = __float2bfloat16(vn);
        g_enf[o] = vn;
    }
}

// ---------------------------------------------------------------------------
__device__ __forceinline__ void mma_f16(float c[4], const unsigned a[4],
                                        const unsigned b[2]) {
    asm volatile(
        "mma.sync.aligned.m16n8k16.row.col.f32.f16.f16.f32 "
        "{%0,%1,%2,%3}, {%4,%5,%6,%7}, {%8,%9}, {%0,%1,%2,%3};"
        : "+f"(c[0]), "+f"(c[1]), "+f"(c[2]), "+f"(c[3])
        : "r"(a[0]), "r"(a[1]), "r"(a[2]), "r"(a[3]), "r"(b[0]), "r"(b[1]));
}
__device__ __forceinline__ void mma_bf16(float c[4], const unsigned a[4],
                                         const unsigned b[2]) {
    asm volatile(
        "mma.sync.aligned.m16n8k16.row.col.f32.bf16.bf16.f32 "
        "{%0,%1,%2,%3}, {%4,%5,%6,%7}, {%8,%9}, {%0,%1,%2,%3};"
        : "+f"(c[0]), "+f"(c[1]), "+f"(c[2]), "+f"(c[3])
        : "r"(a[0]), "r"(a[1]), "r"(a[2]), "r"(a[3]), "r"(b[0]), "r"(b[1]));
}
#define U32P(base, r, k) (*(const unsigned*)((base) + ((r) * AST + (k)) * 2))

// fp16 2-term chunk: acc += Ah*Bh + Al*Bh
__device__ __forceinline__ void mma_chunk_2t(
    const unsigned char* Ah, const unsigned char* Al, const unsigned char* Bh,
    float acc[4][4][4], int wm, int wn, int g, int t) {
    #pragma unroll
    for (int ks = 0; ks < 2; ks++) {
        int k0 = ks * 16;
        unsigned ah[4][4], al[4][4], bh[4][2];
        #pragma unroll
        for (int ma = 0; ma < 4; ma++) {
            int r0 = wm + ma * 16 + g;
            ah[ma][0] = U32P(Ah, r0,     k0 + 2 * t);
            ah[ma][1] = U32P(Ah, r0 + 8, k0 + 2 * t);
            ah[ma][2] = U32P(Ah, r0,     k0 + 2 * t + 8);
            ah[ma][3] = U32P(Ah, r0 + 8, k0 + 2 * t + 8);
            al[ma][0] = U32P(Al, r0,     k0 + 2 * t);
            al[ma][1] = U32P(Al, r0 + 8, k0 + 2 * t);
            al[ma][2] = U32P(Al, r0,     k0 + 2 * t + 8);
            al[ma][3] = U32P(Al, r0 + 8, k0 + 2 * t + 8);
        }
        #pragma unroll
        for (int nb = 0; nb < 4; nb++) {
            int c0 = wn + nb * 8 + g;
            bh[nb][0] = U32P(Bh, c0, k0 + 2 * t);
            bh[nb][1] = U32P(Bh, c0, k0 + 2 * t + 8);
        }
        #pragma unroll
        for (int ma = 0; ma < 4; ma++)
            #pragma unroll
            for (int nb = 0; nb < 4; nb++) {
                mma_f16(acc[ma][nb], ah[ma], bh[nb]);
                mma_f16(acc[ma][nb], al[ma], bh[nb]);
            }
    }
}

__device__ __forceinline__ void mma_chunk_1t(
    const unsigned char* Ah, const unsigned char* Bh,
    float acc[4][4][4], int wm, int wn, int g, int t) {
    #pragma unroll
    for (int ks = 0; ks < 2; ks++) {
        int k0 = ks * 16;
        unsigned ah[4][4], bh[4][2];
        #pragma unroll
        for (int ma = 0; ma < 4; ma++) {
            int r0 = wm + ma * 16 + g;
            ah[ma][0] = U32P(Ah, r0,     k0 + 2 * t);
            ah[ma][1] = U32P(Ah, r0 + 8, k0 + 2 * t);
            ah[ma][2] = U32P(Ah, r0,     k0 + 2 * t + 8);
            ah[ma][3] = U32P(Ah, r0 + 8, k0 + 2 * t + 8);
        }
        #pragma unroll
        for (int nb = 0; nb < 4; nb++) {
            int c0 = wn + nb * 8 + g;
            bh[nb][0] = U32P(Bh, c0, k0 + 2 * t);
            bh[nb][1] = U32P(Bh, c0, k0 + 2 * t + 8);
        }
        #pragma unroll
        for (int ma = 0; ma < 4; ma++)
            #pragma unroll
            for (int nb = 0; nb < 4; nb++)
                mma_bf16(acc[ma][nb], ah[ma], bh[nb]);
    }
}

// ---------------------------------------------------------------------------
// adj: upper-tri tiles, fp16 2-term, cp.async double buffer, mirror writes.
// (unchanged from R11)
// ---------------------------------------------------------------------------
#define ADJ_SMEM (2 * 3 * BUFB)

__global__ void __launch_bounds__(256) adj_sym_kernel(float* __restrict__ out, int N) {
    extern __shared__ __align__(16) unsigned char dsm[];
    float (*S)[SST] = (float(*)[SST])dsm;

    const int T = N / TILE;
    int tt = blockIdx.x;
    int bi = 0;
    while (tt >= (T - bi)) { tt -= (T - bi); bi++; }
    int bj = bi + tt;

    int tid = threadIdx.x;
    int warp = tid >> 5, lane = tid & 31;
    int g = lane >> 2, t = lane & 3;
    int wm = (warp >> 2) * 64;
    int wn = (warp & 3) * 32;
    int lrow = tid >> 1;
    int lk = (tid & 1) * 16;

    const __half* srcs[3] = {
        g_zh + (size_t)bi * TILE * KDIM,
        g_zl + (size_t)bi * TILE * KDIM,
        g_zh + (size_t)bj * TILE * KDIM };

    unsigned sm_row = (unsigned)((lrow * AST + lk) * 2);
    unsigned sbase = (unsigned)__cvta_generic_to_shared(dsm);

    {
        size_t goff = (size_t)lrow * KDIM + lk;
        #pragma unroll
        for (int a = 0; a < 3; a++) {
            unsigned sa = sbase + a * BUFB + sm_row;
            CP16(sa,      srcs[a] + goff);
            CP16(sa + 16, srcs[a] + goff + 8);
        }
        CP_COMMIT();
    }

    float acc[4][4][4];
    #pragma unroll
    for (int ma = 0; ma < 4; ma++)
        #pragma unroll
        for (int nb = 0; nb < 4; nb++)
            #pragma unroll
            for (int q = 0; q < 4; q++) acc[ma][nb][q] = 0.f;

    for (int q = 0; q < 8; q++) {
        CP_WAIT0();
        __syncthreads();
        if (q < 7) {
            size_t goff = (size_t)lrow * KDIM + (q + 1) * 32 + lk;
            unsigned boff = ((q + 1) & 1) * 3 * BUFB;
            #pragma unroll
            for (int a = 0; a < 3; a++) {
                unsigned sa = sbase + boff + a * BUFB + sm_row;
                CP16(sa,      srcs[a] + goff);
                CP16(sa + 16, srcs[a] + goff + 8);
            }
            CP_COMMIT();
        }
        const unsigned char* b = dsm + (q & 1) * 3 * BUFB;
        mma_chunk_2t(b, b + BUFB, b + 2 * BUFB, acc, wm, wn, g, t);
    }

    #pragma unroll
    for (int ma = 0; ma < 4; ma++)
        #pragma unroll
        for (int nb = 0; nb < 4; nb++)
            #pragma unroll
            for (int q = 0; q < 4; q++)
                acc[ma][nb][q] = sigmoid_fast(acc[ma][nb][q]);

    #pragma unroll
    for (int ma = 0; ma < 4; ma++) {
        size_t r0 = (size_t)bi * TILE + wm + ma * 16 + g;
        #pragma unroll
        for (int nb = 0; nb < 4; nb++) {
            size_t c = (size_t)bj * TILE + wn + nb * 8 + 2 * t;
            *(float2*)(out + r0 * N + c)       = make_float2(acc[ma][nb][0], acc[ma][nb][1]);
            *(float2*)(out + (r0 + 8) * N + c) = make_float2(acc[ma][nb][2], acc[ma][nb][3]);
        }
    }

    if (bi == bj) return;

    int myHalf = (warp & 3) >> 1;
    #pragma unroll
    for (int ch = 0; ch < 2; ch++) {
        __syncthreads();
        if (myHalf == ch) {
            int cl = (warp & 1) * 32;
            #pragma unroll
            for (int ma = 0; ma < 4; ma++) {
                int r = wm + ma * 16 + g;
                #pragma unroll
                for (int nb = 0; nb < 4; nb++) {
                    int c = cl + nb * 8 + 2 * t;
                    S[c][r]         = acc[ma][nb][0];
                    S[c + 1][r]     = acc[ma][nb][1];
                    S[c][r + 8]     = acc[ma][nb][2];
                    S[c + 1][r + 8] = acc[ma][nb][3];
                }
            }
        }
        __syncthreads();
        #pragma unroll
        for (int q = 0; q < 8; q++) {
            int idx = tid + 256 * q;
            int mr = idx >> 5;
            int fc = idx & 31;
            size_t grow = (size_t)bj * TILE + ch * 64 + mr;
            *(float4*)(out + grow * N + (size_t)bi * TILE + fc * 4) =
                *(const float4*)&S[mr][fc * 4];
        }
    }
}

// ---------------------------------------------------------------------------
// cos fused: 1-term bf16 GEMM over this block's column split with running
// per-row max + margin-band candidate capture. No cosine matrix stored.
// grid (NSPLIT, N/128). Dynamic smem layout:
//   [0, 40960)           : 2 x 2 operand buffers
//   [40960, 41472)       : unsigned rmax[128]
//   [41472, 41488)       : int cnt (+pad)
//   [41488, 45584)       : int  ccol[BCAP]  (localrow<<16 | col)
//   [45584, 49680)       : float cval[BCAP]
// ---------------------------------------------------------------------------
#define COS_SMEM 49680

__global__ void __launch_bounds__(256) cos_kernel(int N, int V) {
    extern __shared__ __align__(16) unsigned char dsm[];
    unsigned* s_rmax = (unsigned*)(dsm + 40960);
    int*      s_cnt  = (int*)(dsm + 41472);
    int*      s_ccol = (int*)(dsm + 41488);
    float*    s_cval = (float*)(dsm + 45584);

    int tid = threadIdx.x;
    int warp = tid >> 5, lane = tid & 31;
    int g = lane >> 2, t = lane & 3;
    int wm = (warp >> 2) * 64;
    int wn = (warp & 3) * 32;
    int bi = blockIdx.y;
    int split = blockIdx.x;
    int lrow = tid >> 1;
    int lk = (tid & 1) * 16;

    const int colsPerSplit = VMAX / NSPLIT;        // 512
    const int tiles = colsPerSplit / TILE;         // 4
    const int base0 = split * colsPerSplit;

    if (tid < 128) s_rmax[tid] = fenc(-2.0f);
    if (tid == 0) *s_cnt = 0;
    __syncthreads();

    const __nv_bfloat16* aH = g_znh + (size_t)bi * TILE * KDIM;
    unsigned sm_row = (unsigned)((lrow * AST + lk) * 2);
    unsigned sbase = (unsigned)__cvta_generic_to_shared(dsm);

    for (int ct = 0; ct < tiles; ct++) {
        int cbase = base0 + ct * TILE;
        const __nv_bfloat16* bH = g_enh + (size_t)cbase * KDIM;

        // prologue
        {
            size_t goff = (size_t)lrow * KDIM + lk;
            CP16(sbase + sm_row,               aH + goff);
            CP16(sbase + sm_row + 16,          aH + goff + 8);
            CP16(sbase + BUFB + sm_row,        bH + goff);
            CP16(sbase + BUFB + sm_row + 16,   bH + goff + 8);
            CP_COMMIT();
        }

        float acc[4][4][4];
        #pragma unroll
        for (int ma = 0; ma < 4; ma++)
            #pragma unroll
            for (int nb = 0; nb < 4; nb++)
                #pragma unroll
                for (int q = 0; q < 4; q++) acc[ma][nb][q] = 0.f;

        for (int q = 0; q < 8; q++) {
            CP_WAIT0();
            __syncthreads();
            if (q < 7) {
                size_t goff = (size_t)lrow * KDIM + (q + 1) * 32 + lk;
                unsigned boff = ((q + 1) & 1) * 2 * BUFB;
                CP16(sbase + boff + sm_row,             aH + goff);
                CP16(sbase + boff + sm_row + 16,        aH + goff + 8);
                CP16(sbase + boff + BUFB + sm_row,      bH + goff);
                CP16(sbase + boff + BUFB + sm_row + 16, bH + goff + 8);
                CP_COMMIT();
            }
            const unsigned char* b = dsm + (q & 1) * 2 * BUFB;
            mma_chunk_1t(b, b + BUFB, acc, wm, wn, g, t);
        }

        // ---- candidate capture for this tile ----
        // 1) update running per-row max
        #pragma unroll
        for (int ma = 0; ma < 4; ma++) {
            #pragma unroll
            for (int h = 0; h < 2; h++) {
                float m = -2.0f;
                #pragma unroll
                for (int nb = 0; nb < 4; nb++) {
                    m = fmaxf(m, acc[ma][nb][h * 2 + 0]);
                    m = fmaxf(m, acc[ma][nb][h * 2 + 1]);
                }
                #pragma unroll
                for (int off = 2; off; off >>= 1)
                    m = fmaxf(m, __shfl_xor_sync(0xffffffffu, m, off, 4));
                if (t == 0)
                    atomicMax(&s_rmax[wm + ma * 16 + g + h * 8], fenc(m));
            }
        }
        __syncthreads();
        // 2) margin-band append (running max <= final max => superset)
        #pragma unroll
        for (int ma = 0; ma < 4; ma++) {
            #pragma unroll
            for (int h = 0; h < 2; h++) {
                int r = wm + ma * 16 + g + h * 8;
                float thr = fdec(s_rmax[r]) - MARGIN;
                #pragma unroll
                for (int nb = 0; nb < 4; nb++) {
                    int c = cbase + wn + nb * 8 + 2 * t;
                    #pragma unroll
                    for (int qq = 0; qq < 2; qq++) {
                        float v = acc[ma][nb][h * 2 + qq];
                        if (v >= thr) {
                            int pos = atomicAdd(s_cnt, 1);
                            if (pos < BCAP) {
                                s_ccol[pos] = (r << 16) | (c + qq);
                                s_cval[pos] = v;
                            }
                        }
                    }
                }
            }
        }
        __syncthreads();
    }

    // flush block candidates to per-row global lists
    int nlocal = min(*s_cnt, BCAP);
    for (int i = tid; i < nlocal; i += 256) {
        int packed = s_ccol[i];
        int r = packed >> 16;
        int c = packed & 0xFFFF;
        int grow = bi * TILE + r;
        int pos = atomicAdd(&g_ccnt[grow], 1);
        if (pos < CAP) {
            g_ccol[grow][pos] = c;
            g_cval[grow][pos] = s_cval[i];
        }
    }
}

// ---------------------------------------------------------------------------
// Rescore: per row, exact sequential-fmaf dots of candidates within MARGIN
// of the best stored approx value; parallel over candidates; deterministic
// (max value, then min index) selection.
// ---------------------------------------------------------------------------
__global__ void __launch_bounds__(256) rescore_kernel(float* __restrict__ out,
                                                      int N, int V) {
    int row = blockIdx.x;
    int tid = threadIdx.x;

    __shared__ float s_z[KDIM];
    __shared__ float s_d[CAP];
    __shared__ int   s_c[CAP];
    __shared__ float s_gmax;

    s_z[tid] = g_znf[(size_t)row * KDIM + tid];
    __syncthreads();

    int nc = min(g_ccnt[row], CAP);

    if (tid == 0) {
        float gm = -3.0f;
        for (int i = 0; i < nc; i++) gm = fmaxf(gm, g_cval[row][i]);
        s_gmax = gm;
    }
    __syncthreads();
    float thr = s_gmax - MARGIN;

    // parallel exact dots (sequential f32 chain per candidate, k ascending)
    if (tid < nc) {
        float v = g_cval[row][tid];
        int   c = g_ccol[row][tid];
        float d = -3.0f;
        if (v >= thr) {
            const float* e = g_enf + (size_t)c * KDIM;
            d = 0.f;
            #pragma unroll 8
            for (int k = 0; k < KDIM; k++) d = fmaf(s_z[k], e[k], d);
        }
        s_d[tid] = d;
        s_c[tid] = c;
    }
    __syncthreads();

    if (tid == 0) {
        float bv = -4.0f;
        int   bc = 0x7fffffff;
        for (int i = 0; i < nc; i++) {
            float d = s_d[i];
            int   c = s_c[i];
            if (d > bv || (d == bv && c < bc)) { bv = d; bc = c; }
        }
        out[(size_t)N * (size_t)N + row] = (float)bc;
    }
}

// ---------------------------------------------------------------------------
extern "C" void kernel_launch(void* const* d_in, const int* in_sizes, int n_in,
                              void* d_out, int out_size) {
    const float* z = (const float*)d_in[0];
    const float* e = (const float*)d_in[1];
    float* out = (float*)d_out;

    int N = in_sizes[0] / KDIM;   // 8192
    int V = in_sizes[1] / KDIM;   // 4096
    int T = N / TILE;             // 64

    cudaFuncSetAttribute(adj_sym_kernel,
                         cudaFuncAttributeMaxDynamicSharedMemorySize, ADJ_SMEM);
    cudaFuncSetAttribute(cos_kernel,
                         cudaFuncAttributeMaxDynamicSharedMemorySize, COS_SMEM);

    prep_kernel<<<N + V, 256>>>(z, e, N, V);

    int nTiles = T * (T + 1) / 2; // 2080
    adj_sym_kernel<<<nTiles, 256, ADJ_SMEM>>>(out, N);

    dim3 gCos(NSPLIT, N / TILE);
    cos_kernel<<<gCos, 256, COS_SMEM>>>(N, V);

    rescore_kernel<<<N, 256>>>(out, N, V);
}

// round 13
// speedup vs baseline: 1.2947x; 1.2947x over previous
#include <cuda_runtime.h>
#include <cuda_bf16.h>
#include <cuda_fp16.h>
#include <math.h>

// z [8192,256] f32, embedding [4096,256] f32.
// out = [ sigmoid(z z^T) (8192x8192 f32) , argmax cosine indices (8192 f32) ]
// adj: fp16 1-term mma.sync (error ~4.4e-4 norm-rel, calibrated), FMA sigmoid.
// cos: bf16 1-term mma.sync -> bf16 approx matrix + fused row-max (R11 proven).
// rescore: vectorized bf16 gather + exact sequential-fmaf dots (R6 proven).
// NOTE: tcgen05 unavailable (harness targets compute_103 without 'a').

#define KDIM 256
#define TILE 128
#define NMAX 8192
#define VMAX 4096
#define AST  40          // smem row stride in elements (80B rows)
#define SST  132         // mirror-staging row stride in f32
#define MARGIN 1.0e-2f   // > bf16-gemm err (3.9e-3) + bf16-store err (2e-3)
#define MAXCAND 256
#define BUFB (TILE * AST * 2)   // 10240 bytes per operand buffer

__device__ __half g_zh [NMAX * KDIM];
__device__ __nv_bfloat16 g_znh[NMAX * KDIM];
__device__ __nv_bfloat16 g_enh[VMAX * KDIM];
__device__ float g_znf[NMAX * KDIM];
__device__ float g_enf[VMAX * KDIM];
__device__ __nv_bfloat16 g_cosb[(size_t)NMAX * VMAX];
__device__ unsigned g_rowmax[NMAX];   // order-preserving float encoding

// ---------------- order-preserving float <-> uint ---------------------------
__device__ __forceinline__ unsigned fenc(float f) {
    unsigned b = __float_as_uint(f);
    return (b & 0x80000000u) ? ~b : (b | 0x80000000u);
}
__device__ __forceinline__ float fdec(unsigned u) {
    return (u & 0x80000000u) ? __uint_as_float(u & 0x7FFFFFFFu)
                             : __uint_as_float(~u);
}

// ---------------- cp.async helpers ------------------------------------------
#define CP16(sa, gp) \
    asm volatile("cp.async.cg.shared.global [%0], [%1], 16;" \
                 :: "r"(sa), "l"(gp) : "memory")
#define CP_COMMIT() asm volatile("cp.async.commit_group;" ::: "memory")
#define CP_WAIT0()  asm volatile("cp.async.wait_group 0;" ::: "memory")

// ===================== FMA-only sigmoid (no MUFU) ===========================
__device__ __forceinline__ float sigmoid_fast(float x) {
    float ax = fminf(fabsf(x), 30.0f);
    float u  = ax * 1.4426950408889634f;
    float fm = u + 12582912.0f;
    float n  = fm - 12582912.0f;
    float f  = n - u;
    float p  = 1.3333558146428443e-3f;
    p = fmaf(p, f, 9.6181291976353954e-3f);
    p = fmaf(p, f, 5.5504108664798463e-2f);
    p = fmaf(p, f, 2.4022650695910071e-1f);
    p = fmaf(p, f, 6.9314718055994531e-1f);
    p = fmaf(p, f, 1.0f);
    int nbits = (__float_as_int(fm) & 0x7F) << 23;
    float scale = __int_as_float(0x3F800000 - nbits);
    float q = p * scale;
    float d = 1.0f + q;
    float r = fmaf(d, fmaf(d, 0.33333333f, -1.5f), 2.16666667f);
    r = r * (2.0f - d * r);
    r = r * (2.0f - d * r);
    return (x >= 0.0f) ? r : r * q;
}

// ===================== prep: normalize + splits =============================
__global__ void prep_kernel(const float* __restrict__ z,
                            const float* __restrict__ e,
                            int N, int V) {
    int row = blockIdx.x;
    int tid = threadIdx.x;
    bool isZ = row < N;
    const float* src = isZ ? (z + (size_t)row * KDIM)
                           : (e + (size_t)(row - N) * KDIM);
    float v = src[tid];

    float ss = v * v;
    #pragma unroll
    for (int o = 16; o; o >>= 1) ss += __shfl_xor_sync(0xffffffffu, ss, o);
    __shared__ float s_partial[8];
    __shared__ float s_total;
    if ((tid & 31) == 0) s_partial[tid >> 5] = ss;
    __syncthreads();
    if (tid == 0) {
        float t = 0.f;
        #pragma unroll
        for (int i = 0; i < 8; i++) t += s_partial[i];
        s_total = t;
    }
    __syncthreads();
    float inv = 1.0f / fmaxf(sqrtf(s_total), 1e-8f);
    float vn = v * inv;

    if (isZ) {
        size_t o = (size_t)row * KDIM + tid;
        g_zh[o] = __float2half_rn(v);
        g_znh[o] = __float2bfloat16(vn);
        g_znf[o] = vn;
        if (tid == 0) g_rowmax[row] = 0u;   // reset per launch
    } else {
        size_t o = (size_t)(row - N) * KDIM + tid;
        g_enh[o] = __float2bfloat16(vn);
        g_enf[o] = vn;
    }
}

// ---------------------------------------------------------------------------
__device__ __forceinline__ void mma_f16(float c[4], const unsigned a[4],
                                        const unsigned b[2]) {
    asm volatile(
        "mma.sync.aligned.m16n8k16.row.col.f32.f16.f16.f32 "
        "{%0,%1,%2,%3}, {%4,%5,%6,%7}, {%8,%9}, {%0,%1,%2,%3};"
        : "+f"(c[0]), "+f"(c[1]), "+f"(c[2]), "+f"(c[3])
        : "r"(a[0]), "r"(a[1]), "r"(a[2]), "r"(a[3]), "r"(b[0]), "r"(b[1]));
}
__device__ __forceinline__ void mma_bf16(float c[4], const unsigned a[4],
                                         const unsigned b[2]) {
    asm volatile(
        "mma.sync.aligned.m16n8k16.row.col.f32.bf16.bf16.f32 "
        "{%0,%1,%2,%3}, {%4,%5,%6,%7}, {%8,%9}, {%0,%1,%2,%3};"
        : "+f"(c[0]), "+f"(c[1]), "+f"(c[2]), "+f"(c[3])
        : "r"(a[0]), "r"(a[1]), "r"(a[2]), "r"(a[3]), "r"(b[0]), "r"(b[1]));
}
#define U32P(base, r, k) (*(const unsigned*)((base) + ((r) * AST + (k)) * 2))

// 1-term fp16 chunk: acc += A*B
__device__ __forceinline__ void mma_chunk_1t_f16(
    const unsigned char* Ah, const unsigned char* Bh,
    float acc[4][4][4], int wm, int wn, int g, int t) {
    #pragma unroll
    for (int ks = 0; ks < 2; ks++) {
        int k0 = ks * 16;
        unsigned ah[4][4], bh[4][2];
        #pragma unroll
        for (int ma = 0; ma < 4; ma++) {
            int r0 = wm + ma * 16 + g;
            ah[ma][0] = U32P(Ah, r0,     k0 + 2 * t);
            ah[ma][1] = U32P(Ah, r0 + 8, k0 + 2 * t);
            ah[ma][2] = U32P(Ah, r0,     k0 + 2 * t + 8);
            ah[ma][3] = U32P(Ah, r0 + 8, k0 + 2 * t + 8);
        }
        #pragma unroll
        for (int nb = 0; nb < 4; nb++) {
            int c0 = wn + nb * 8 + g;
            bh[nb][0] = U32P(Bh, c0, k0 + 2 * t);
            bh[nb][1] = U32P(Bh, c0, k0 + 2 * t + 8);
        }
        #pragma unroll
        for (int ma = 0; ma < 4; ma++)
            #pragma unroll
            for (int nb = 0; nb < 4; nb++)
                mma_f16(acc[ma][nb], ah[ma], bh[nb]);
    }
}

// 1-term bf16 chunk
__device__ __forceinline__ void mma_chunk_1t_bf16(
    const unsigned char* Ah, const unsigned char* Bh,
    float acc[4][4][4], int wm, int wn, int g, int t) {
    #pragma unroll
    for (int ks = 0; ks < 2; ks++) {
        int k0 = ks * 16;
        unsigned ah[4][4], bh[4][2];
        #pragma unroll
        for (int ma = 0; ma < 4; ma++) {
            int r0 = wm + ma * 16 + g;
            ah[ma][0] = U32P(Ah, r0,     k0 + 2 * t);
            ah[ma][1] = U32P(Ah, r0 + 8, k0 + 2 * t);
            ah[ma][2] = U32P(Ah, r0,     k0 + 2 * t + 8);
            ah[ma][3] = U32P(Ah, r0 + 8, k0 + 2 * t + 8);
        }
        #pragma unroll
        for (int nb = 0; nb < 4; nb++) {
            int c0 = wn + nb * 8 + g;
            bh[nb][0] = U32P(Bh, c0, k0 + 2 * t);
            bh[nb][1] = U32P(Bh, c0, k0 + 2 * t + 8);
        }
        #pragma unroll
        for (int ma = 0; ma < 4; ma++)
            #pragma unroll
            for (int nb = 0; nb < 4; nb++)
                mma_bf16(acc[ma][nb], ah[ma], bh[nb]);
    }
}

// ---------------------------------------------------------------------------
// adj: upper-tri tiles, fp16 1-term, cp.async double buffer, mirror writes.
// ---------------------------------------------------------------------------
#define ADJ_SMEM (2 * 2 * BUFB)

__global__ void __launch_bounds__(256) adj_sym_kernel(float* __restrict__ out, int N) {
    extern __shared__ __align__(16) unsigned char dsm[];
    float (*S)[SST] = (float(*)[SST])dsm;

    const int T = N / TILE;
    int tt = blockIdx.x;
    int bi = 0;
    while (tt >= (T - bi)) { tt -= (T - bi); bi++; }
    int bj = bi + tt;

    int tid = threadIdx.x;
    int warp = tid >> 5, lane = tid & 31;
    int g = lane >> 2, t = lane & 3;
    int wm = (warp >> 2) * 64;
    int wn = (warp & 3) * 32;
    int lrow = tid >> 1;
    int lk = (tid & 1) * 16;

    const __half* srcs[2] = {
        g_zh + (size_t)bi * TILE * KDIM,
        g_zh + (size_t)bj * TILE * KDIM };

    unsigned sm_row = (unsigned)((lrow * AST + lk) * 2);
    unsigned sbase = (unsigned)__cvta_generic_to_shared(dsm);

    {
        size_t goff = (size_t)lrow * KDIM + lk;
        #pragma unroll
        for (int a = 0; a < 2; a++) {
            unsigned sa = sbase + a * BUFB + sm_row;
            CP16(sa,      srcs[a] + goff);
            CP16(sa + 16, srcs[a] + goff + 8);
        }
        CP_COMMIT();
    }

    float acc[4][4][4];
    #pragma unroll
    for (int ma = 0; ma < 4; ma++)
        #pragma unroll
        for (int nb = 0; nb < 4; nb++)
            #pragma unroll
            for (int q = 0; q < 4; q++) acc[ma][nb][q] = 0.f;

    for (int q = 0; q < 8; q++) {
        CP_WAIT0();
        __syncthreads();
        if (q < 7) {
            size_t goff = (size_t)lrow * KDIM + (q + 1) * 32 + lk;
            unsigned boff = ((q + 1) & 1) * 2 * BUFB;
            #pragma unroll
            for (int a = 0; a < 2; a++) {
                unsigned sa = sbase + boff + a * BUFB + sm_row;
                CP16(sa,      srcs[a] + goff);
                CP16(sa + 16, srcs[a] + goff + 8);
            }
            CP_COMMIT();
        }
        const unsigned char* b = dsm + (q & 1) * 2 * BUFB;
        mma_chunk_1t_f16(b, b + BUFB, acc, wm, wn, g, t);
    }

    #pragma unroll
    for (int ma = 0; ma < 4; ma++)
        #pragma unroll
        for (int nb = 0; nb < 4; nb++)
            #pragma unroll
            for (int q = 0; q < 4; q++)
                acc[ma][nb][q] = sigmoid_fast(acc[ma][nb][q]);

    #pragma unroll
    for (int ma = 0; ma < 4; ma++) {
        size_t r0 = (size_t)bi * TILE + wm + ma * 16 + g;
        #pragma unroll
        for (int nb = 0; nb < 4; nb++) {
            size_t c = (size_t)bj * TILE + wn + nb * 8 + 2 * t;
            *(float2*)(out + r0 * N + c)       = make_float2(acc[ma][nb][0], acc[ma][nb][1]);
            *(float2*)(out + (r0 + 8) * N + c) = make_float2(acc[ma][nb][2], acc[ma][nb][3]);
        }
    }

    if (bi == bj) return;

    int myHalf = (warp & 3) >> 1;
    #pragma unroll
    for (int ch = 0; ch < 2; ch++) {
        __syncthreads();
        if (myHalf == ch) {
            int cl = (warp & 1) * 32;
            #pragma unroll
            for (int ma = 0; ma < 4; ma++) {
                int r = wm + ma * 16 + g;
                #pragma unroll
                for (int nb = 0; nb < 4; nb++) {
                    int c = cl + nb * 8 + 2 * t;
                    S[c][r]         = acc[ma][nb][0];
                    S[c + 1][r]     = acc[ma][nb][1];
                    S[c][r + 8]     = acc[ma][nb][2];
                    S[c + 1][r + 8] = acc[ma][nb][3];
                }
            }
        }
        __syncthreads();
        #pragma unroll
        for (int q = 0; q < 8; q++) {
            int idx = tid + 256 * q;
            int mr = idx >> 5;
            int fc = idx & 31;
            size_t grow = (size_t)bj * TILE + ch * 64 + mr;
            *(float4*)(out + grow * N + (size_t)bi * TILE + fc * 4) =
                *(const float4*)&S[mr][fc * 4];
        }
    }
}

// ---------------------------------------------------------------------------
// cos: 1-term bf16 GEMM -> bf16 matrix + fused per-row atomic max (on the
// ROUNDED values, so rescore sees a consistent ordering). (R11 proven)
// ---------------------------------------------------------------------------
__global__ void __launch_bounds__(256) cos_kernel(int N, int V) {
    __shared__ __align__(16) unsigned char csm[2 * 2 * BUFB];

    int tid = threadIdx.x;
    int warp = tid >> 5, lane = tid & 31;
    int g = lane >> 2, t = lane & 3;
    int wm = (warp >> 2) * 64;
    int wn = (warp & 3) * 32;
    int bi = blockIdx.y;
    int bj = blockIdx.x;
    int lrow = tid >> 1;
    int lk = (tid & 1) * 16;

    const __nv_bfloat16* srcs[2] = {
        g_znh + (size_t)bi * TILE * KDIM, g_enh + (size_t)bj * TILE * KDIM };

    unsigned sm_row = (unsigned)((lrow * AST + lk) * 2);
    unsigned sbase = (unsigned)__cvta_generic_to_shared(csm);

    {
        size_t goff = (size_t)lrow * KDIM + lk;
        #pragma unroll
        for (int a = 0; a < 2; a++) {
            unsigned sa = sbase + a * BUFB + sm_row;
            CP16(sa,      srcs[a] + goff);
            CP16(sa + 16, srcs[a] + goff + 8);
        }
        CP_COMMIT();
    }

    float acc[4][4][4];
    #pragma unroll
    for (int ma = 0; ma < 4; ma++)
        #pragma unroll
        for (int nb = 0; nb < 4; nb++)
            #pragma unroll
            for (int q = 0; q < 4; q++) acc[ma][nb][q] = 0.f;

    for (int q = 0; q < 8; q++) {
        CP_WAIT0();
        __syncthreads();
        if (q < 7) {
            size_t goff = (size_t)lrow * KDIM + (q + 1) * 32 + lk;
            unsigned boff = ((q + 1) & 1) * 2 * BUFB;
            #pragma unroll
            for (int a = 0; a < 2; a++) {
                unsigned sa = sbase + boff + a * BUFB + sm_row;
                CP16(sa,      srcs[a] + goff);
                CP16(sa + 16, srcs[a] + goff + 8);
            }
            CP_COMMIT();
        }
        const unsigned char* b = csm + (q & 1) * 2 * BUFB;
        mma_chunk_1t_bf16(b, b + BUFB, acc, wm, wn, g, t);
    }

    #pragma unroll
    for (int ma = 0; ma < 4; ma++) {
        size_t r0 = (size_t)bi * TILE + wm + ma * 16 + g;
        #pragma unroll
        for (int h = 0; h < 2; h++) {
            size_t rr = r0 + h * 8;
            float m = -2.0f;
            #pragma unroll
            for (int nb = 0; nb < 4; nb++) {
                size_t c = (size_t)bj * TILE + wn + nb * 8 + 2 * t;
                unsigned lo = (unsigned)__bfloat16_as_ushort(
                    __float2bfloat16(acc[ma][nb][h * 2 + 0]));
                unsigned hi = (unsigned)__bfloat16_as_ushort(
                    __float2bfloat16(acc[ma][nb][h * 2 + 1]));
                *(unsigned*)(g_cosb + rr * V + c) = lo | (hi << 16);
                m = fmaxf(m, __uint_as_float(lo << 16));
                m = fmaxf(m, __uint_as_float(hi << 16));
            }
            #pragma unroll
            for (int off = 2; off; off >>= 1)
                m = fmaxf(m, __shfl_xor_sync(0xffffffffu, m, off, 4));
            if (t == 0)
                atomicMax(&g_rowmax[rr], fenc(m));
        }
    }
}

// ---------------------------------------------------------------------------
// Rescore: vectorized bf16 gather (threshold from g_rowmax) + exact
// sequential fmaf-chain dots, smallest-index tie-break. (R11 proven)
// ---------------------------------------------------------------------------
__global__ void __launch_bounds__(256) rescore_kernel(float* __restrict__ out,
                                                      int N, int V) {
    int row = blockIdx.x;
    int tid = threadIdx.x;
    const uint4* crow = (const uint4*)(g_cosb + (size_t)row * V);  // 8 bf16 each

    __shared__ int   s_cnt;
    __shared__ int   s_cand[MAXCAND];
    __shared__ float s_z[KDIM];
    __shared__ float s_e[KDIM];
    __shared__ float s_bestv;
    __shared__ int   s_besti;

    s_z[tid] = g_znf[(size_t)row * KDIM + tid];
    if (tid == 0) { s_cnt = 0; s_bestv = -3.0f; s_besti = 0x7fffffff; }
    __syncthreads();

    float thr = fdec(g_rowmax[row]) - MARGIN;

    int nvec = V / 8;   // 512
    for (int i = tid; i < nvec; i += 256) {
        uint4 w = crow[i];
        unsigned u[4] = {w.x, w.y, w.z, w.w};
        int cbase = i * 8;
        #pragma unroll
        for (int j = 0; j < 4; j++) {
            float v0 = __uint_as_float(u[j] << 16);
            float v1 = __uint_as_float(u[j] & 0xFFFF0000u);
            if (v0 >= thr) {
                int pos = atomicAdd(&s_cnt, 1);
                if (pos < MAXCAND) s_cand[pos] = cbase + 2 * j;
            }
            if (v1 >= thr) {
                int pos = atomicAdd(&s_cnt, 1);
                if (pos < MAXCAND) s_cand[pos] = cbase + 2 * j + 1;
            }
        }
    }
    __syncthreads();
    int nc = min(s_cnt, MAXCAND);

    for (int i = 0; i < nc; i++) {
        int c = s_cand[i];
        s_e[tid] = g_enf[(size_t)c * KDIM + tid];
        __syncthreads();
        if (tid == 0) {
            float d = 0.f;
            #pragma unroll 8
            for (int k = 0; k < KDIM; k++) d = fmaf(s_z[k], s_e[k], d);
            if (d > s_bestv || (d == s_bestv && c < s_besti)) {
                s_bestv = d; s_besti = c;
            }
        }
        __syncthreads();
    }

    if (tid == 0) out[(size_t)N * (size_t)N + row] = (float)s_besti;
}

// ---------------------------------------------------------------------------
extern "C" void kernel_launch(void* const* d_in, const int* in_sizes, int n_in,
                              void* d_out, int out_size) {
    const float* z = (const float*)d_in[0];
    const float* e = (const float*)d_in[1];
    float* out = (float*)d_out;

    int N = in_sizes[0] / KDIM;   // 8192
    int V = in_sizes[1] / KDIM;   // 4096
    int T = N / TILE;             // 64

    cudaFuncSetAttribute(adj_sym_kernel,
                         cudaFuncAttributeMaxDynamicSharedMemorySize, ADJ_SMEM);

    prep_kernel<<<N + V, 256>>>(z, e, N, V);

    int nTiles = T * (T + 1) / 2; // 2080
    adj_sym_kernel<<<nTiles, 256, ADJ_SMEM>>>(out, N);

    dim3 gCos(V / TILE, N / TILE);
    cos_kernel<<<gCos, 256>>>(N, V);

    rescore_kernel<<<N, 256>>>(out, N, V);
}

// round 15
// speedup vs baseline: 1.5113x; 1.1673x over previous
#include <cuda_runtime.h>
#include <cuda_bf16.h>
#include <cuda_fp16.h>
#include <math.h>

// z [8192,256] f32, embedding [4096,256] f32.
// out = [ sigmoid(z z^T) (8192x8192 f32) , argmax cosine indices (8192 f32) ]
// adj: fp16 1-term mma.sync + ldmatrix fragments, FMA sigmoid, sym tiles.
// cos: bf16 1-term mma.sync + ldmatrix -> bf16 matrix + fused row-max.
// rescore: vectorized gather + warp-parallel exact sequential-fmaf dots.
// NOTE: tcgen05 unavailable (harness targets compute_103 without 'a').

#define KDIM 256
#define TILE 128
#define NMAX 8192
#define VMAX 4096
#define AST  40          // smem row stride in elements (80B rows, LDSM conflict-free)
#define SST  132         // mirror-staging row stride in f32
#define MARGIN 1.0e-2f   // > bf16-gemm err (3.9e-3) + bf16-store err (2e-3)
#define MAXCAND 256
#define BUFB (TILE * AST * 2)   // 10240 bytes per operand buffer

__device__ __half g_zh [NMAX * KDIM];
__device__ __nv_bfloat16 g_znh[NMAX * KDIM];
__device__ __nv_bfloat16 g_enh[VMAX * KDIM];
__device__ float g_znf[NMAX * KDIM];
__device__ float g_enf[VMAX * KDIM];
__device__ __nv_bfloat16 g_cosb[(size_t)NMAX * VMAX];
__device__ unsigned g_rowmax[NMAX];   // order-preserving float encoding

// ---------------- order-preserving float <-> uint ---------------------------
__device__ __forceinline__ unsigned fenc(float f) {
    unsigned b = __float_as_uint(f);
    return (b & 0x80000000u) ? ~b : (b | 0x80000000u);
}
__device__ __forceinline__ float fdec(unsigned u) {
    return (u & 0x80000000u) ? __uint_as_float(u & 0x7FFFFFFFu)
                             : __uint_as_float(~u);
}

// ---------------- cp.async helpers ------------------------------------------
#define CP16(sa, gp) \
    asm volatile("cp.async.cg.shared.global [%0], [%1], 16;" \
                 :: "r"(sa), "l"(gp) : "memory")
#define CP_COMMIT() asm volatile("cp.async.commit_group;" ::: "memory")
#define CP_WAIT0()  asm volatile("cp.async.wait_group 0;" ::: "memory")

// ===================== FMA-only sigmoid (no MUFU) ===========================
__device__ __forceinline__ float sigmoid_fast(float x) {
    float ax = fminf(fabsf(x), 30.0f);
    float u  = ax * 1.4426950408889634f;
    float fm = u + 12582912.0f;
    float n  = fm - 12582912.0f;
    float f  = n - u;
    float p  = 1.3333558146428443e-3f;
    p = fmaf(p, f, 9.6181291976353954e-3f);
    p = fmaf(p, f, 5.5504108664798463e-2f);
    p = fmaf(p, f, 2.4022650695910071e-1f);
    p = fmaf(p, f, 6.9314718055994531e-1f);
    p = fmaf(p, f, 1.0f);
    int nbits = (__float_as_int(fm) & 0x7F) << 23;
    float scale = __int_as_float(0x3F800000 - nbits);
    float q = p * scale;
    float d = 1.0f + q;
    float r = fmaf(d, fmaf(d, 0.33333333f, -1.5f), 2.16666667f);
    r = r * (2.0f - d * r);
    r = r * (2.0f - d * r);
    return (x >= 0.0f) ? r : r * q;
}

// ===================== prep: normalize + splits =============================
__global__ void prep_kernel(const float* __restrict__ z,
                            const float* __restrict__ e,
                            int N, int V) {
    int row = blockIdx.x;
    int tid = threadIdx.x;
    bool isZ = row < N;
    const float* src = isZ ? (z + (size_t)row * KDIM)
                           : (e + (size_t)(row - N) * KDIM);
    float v = src[tid];

    float ss = v * v;
    #pragma unroll
    for (int o = 16; o; o >>= 1) ss += __shfl_xor_sync(0xffffffffu, ss, o);
    __shared__ float s_partial[8];
    __shared__ float s_total;
    if ((tid & 31) == 0) s_partial[tid >> 5] = ss;
    __syncthreads();
    if (tid == 0) {
        float t = 0.f;
        #pragma unroll
        for (int i = 0; i < 8; i++) t += s_partial[i];
        s_total = t;
    }
    __syncthreads();
    float inv = 1.0f / fmaxf(sqrtf(s_total), 1e-8f);
    float vn = v * inv;

    if (isZ) {
        size_t o = (size_t)row * KDIM + tid;
        g_zh[o] = __float2half_rn(v);
        g_znh[o] = __float2bfloat16(vn);
        g_znf[o] = vn;
        if (tid == 0) g_rowmax[row] = 0u;   // reset per launch
    } else {
        size_t o = (size_t)(row - N) * KDIM + tid;
        g_enh[o] = __float2bfloat16(vn);
        g_enf[o] = vn;
    }
}

// ---------------------------------------------------------------------------
__device__ __forceinline__ void mma_f16(float c[4], const unsigned a[4],
                                        const unsigned b[2]) {
    asm volatile(
        "mma.sync.aligned.m16n8k16.row.col.f32.f16.f16.f32 "
        "{%0,%1,%2,%3}, {%4,%5,%6,%7}, {%8,%9}, {%0,%1,%2,%3};"
        : "+f"(c[0]), "+f"(c[1]), "+f"(c[2]), "+f"(c[3])
        : "r"(a[0]), "r"(a[1]), "r"(a[2]), "r"(a[3]), "r"(b[0]), "r"(b[1]));
}
__device__ __forceinline__ void mma_bf16(float c[4], const unsigned a[4],
                                         const unsigned b[2]) {
    asm volatile(
        "mma.sync.aligned.m16n8k16.row.col.f32.bf16.bf16.f32 "
        "{%0,%1,%2,%3}, {%4,%5,%6,%7}, {%8,%9}, {%0,%1,%2,%3};"
        : "+f"(c[0]), "+f"(c[1]), "+f"(c[2]), "+f"(c[3])
        : "r"(a[0]), "r"(a[1]), "r"(a[2]), "r"(a[3]), "r"(b[0]), "r"(b[1]));
}
__device__ __forceinline__ void ldsm_x4(unsigned& d0, unsigned& d1,
                                        unsigned& d2, unsigned& d3,
                                        unsigned addr) {
    asm volatile("ldmatrix.sync.aligned.m8n8.x4.shared.b16 {%0,%1,%2,%3}, [%4];"
                 : "=r"(d0), "=r"(d1), "=r"(d2), "=r"(d3) : "r"(addr));
}

// Fragment load via ldmatrix for one 32-k chunk; smem [128][AST] b16.
__device__ __forceinline__ void load_frags(unsigned sbA, unsigned sbB,
                                           unsigned ah[4][4], unsigned bh[4][2],
                                           int wm, int wn, int lane, int k0) {
    int arow = lane & 15;
    int akoff = k0 + (lane >> 4) * 8;
    #pragma unroll
    for (int ma = 0; ma < 4; ma++) {
        unsigned addr = sbA + (unsigned)(((wm + ma * 16 + arow) * AST + akoff) * 2);
        ldsm_x4(ah[ma][0], ah[ma][1], ah[ma][2], ah[ma][3], addr);
    }
    int bcol = (lane & 7) + ((lane >> 4) << 3);
    int bkoff = k0 + ((lane >> 3) & 1) * 8;
    #pragma unroll
    for (int nbp = 0; nbp < 2; nbp++) {
        unsigned addr = sbB + (unsigned)(((wn + nbp * 16 + bcol) * AST + bkoff) * 2);
        unsigned d0, d1, d2, d3;
        ldsm_x4(d0, d1, d2, d3, addr);
        bh[nbp * 2][0] = d0;     bh[nbp * 2][1] = d1;
        bh[nbp * 2 + 1][0] = d2; bh[nbp * 2 + 1][1] = d3;
    }
}

__device__ __forceinline__ void mma_chunk_f16(unsigned sbA, unsigned sbB,
                                              float acc[4][4][4],
                                              int wm, int wn, int lane) {
    #pragma unroll
    for (int ks = 0; ks < 2; ks++) {
        unsigned ah[4][4], bh[4][2];
        load_frags(sbA, sbB, ah, bh, wm, wn, lane, ks * 16);
        #pragma unroll
        for (int ma = 0; ma < 4; ma++)
            #pragma unroll
            for (int nb = 0; nb < 4; nb++)
                mma_f16(acc[ma][nb], ah[ma], bh[nb]);
    }
}
__device__ __forceinline__ void mma_chunk_bf16(unsigned sbA, unsigned sbB,
                                               float acc[4][4][4],
                                               int wm, int wn, int lane) {
    #pragma unroll
    for (int ks = 0; ks < 2; ks++) {
        unsigned ah[4][4], bh[4][2];
        load_frags(sbA, sbB, ah, bh, wm, wn, lane, ks * 16);
        #pragma unroll
        for (int ma = 0; ma < 4; ma++)
            #pragma unroll
            for (int nb = 0; nb < 4; nb++)
                mma_bf16(acc[ma][nb], ah[ma], bh[nb]);
    }
}

// ---------------------------------------------------------------------------
// adj: upper-tri tiles, fp16 1-term, cp.async double buffer, mirror writes.
// ---------------------------------------------------------------------------
#define ADJ_SMEM (2 * 2 * BUFB)

__global__ void __launch_bounds__(256) adj_sym_kernel(float* __restrict__ out, int N) {
    extern __shared__ __align__(16) unsigned char dsm[];
    float (*S)[SST] = (float(*)[SST])dsm;

    const int T = N / TILE;
    int tt = blockIdx.x;
    int bi = 0;
    while (tt >= (T - bi)) { tt -= (T - bi); bi++; }
    int bj = bi + tt;

    int tid = threadIdx.x;
    int warp = tid >> 5, lane = tid & 31;
    int g = lane >> 2, t = lane & 3;
    int wm = (warp >> 2) * 64;
    int wn = (warp & 3) * 32;
    int lrow = tid >> 1;
    int lk = (tid & 1) * 16;

    const __half* srcs[2] = {
        g_zh + (size_t)bi * TILE * KDIM,
        g_zh + (size_t)bj * TILE * KDIM };

    unsigned sm_row = (unsigned)((lrow * AST + lk) * 2);
    unsigned sbase = (unsigned)__cvta_generic_to_shared(dsm);

    {
        size_t goff = (size_t)lrow * KDIM + lk;
        #pragma unroll
        for (int a = 0; a < 2; a++) {
            unsigned sa = sbase + a * BUFB + sm_row;
            CP16(sa,      srcs[a] + goff);
            CP16(sa + 16, srcs[a] + goff + 8);
        }
        CP_COMMIT();
    }

    float acc[4][4][4];
    #pragma unroll
    for (int ma = 0; ma < 4; ma++)
        #pragma unroll
        for (int nb = 0; nb < 4; nb++)
            #pragma unroll
            for (int q = 0; q < 4; q++) acc[ma][nb][q] = 0.f;

    for (int q = 0; q < 8; q++) {
        CP_WAIT0();
        __syncthreads();
        if (q < 7) {
            size_t goff = (size_t)lrow * KDIM + (q + 1) * 32 + lk;
            unsigned boff = ((q + 1) & 1) * 2 * BUFB;
            #pragma unroll
            for (int a = 0; a < 2; a++) {
                unsigned sa = sbase + boff + a * BUFB + sm_row;
                CP16(sa,      srcs[a] + goff);
                CP16(sa + 16, srcs[a] + goff + 8);
            }
            CP_COMMIT();
        }
        unsigned bb = sbase + (q & 1) * 2 * BUFB;
        mma_chunk_f16(bb, bb + BUFB, acc, wm, wn, lane);
    }

    #pragma unroll
    for (int ma = 0; ma < 4; ma++)
        #pragma unroll
        for (int nb = 0; nb < 4; nb++)
            #pragma unroll
            for (int q = 0; q < 4; q++)
                acc[ma][nb][q] = sigmoid_fast(acc[ma][nb][q]);

    #pragma unroll
    for (int ma = 0; ma < 4; ma++) {
        size_t r0 = (size_t)bi * TILE + wm + ma * 16 + g;
        #pragma unroll
        for (int nb = 0; nb < 4; nb++) {
            size_t c = (size_t)bj * TILE + wn + nb * 8 + 2 * t;
            *(float2*)(out + r0 * N + c)       = make_float2(acc[ma][nb][0], acc[ma][nb][1]);
            *(float2*)(out + (r0 + 8) * N + c) = make_float2(acc[ma][nb][2], acc[ma][nb][3]);
        }
    }

    if (bi == bj) return;

    int myHalf = (warp & 3) >> 1;
    #pragma unroll
    for (int ch = 0; ch < 2; ch++) {
        __syncthreads();
        if (myHalf == ch) {
            int cl = (warp & 1) * 32;
            #pragma unroll
            for (int ma = 0; ma < 4; ma++) {
                int r = wm + ma * 16 + g;
                #pragma unroll
                for (int nb = 0; nb < 4; nb++) {
                    int c = cl + nb * 8 + 2 * t;
                    S[c][r]         = acc[ma][nb][0];
                    S[c + 1][r]     = acc[ma][nb][1];
                    S[c][r + 8]     = acc[ma][nb][2];
                    S[c + 1][r + 8] = acc[ma][nb][3];
                }
            }
        }
        __syncthreads();
        #pragma unroll
        for (int q = 0; q < 8; q++) {
            int idx = tid + 256 * q;
            int mr = idx >> 5;
            int fc = idx & 31;
            size_t grow = (size_t)bj * TILE + ch * 64 + mr;
            *(float4*)(out + grow * N + (size_t)bi * TILE + fc * 4) =
                *(const float4*)&S[mr][fc * 4];
        }
    }
}

// ---------------------------------------------------------------------------
// cos: 1-term bf16 GEMM (ldmatrix) -> bf16 matrix + fused per-row atomic max.
// ---------------------------------------------------------------------------
__global__ void __launch_bounds__(256) cos_kernel(int N, int V) {
    __shared__ __align__(16) unsigned char csm[2 * 2 * BUFB];

    int tid = threadIdx.x;
    int warp = tid >> 5, lane = tid & 31;
    int g = lane >> 2, t = lane & 3;
    int wm = (warp >> 2) * 64;
    int wn = (warp & 3) * 32;
    int bi = blockIdx.y;
    int bj = blockIdx.x;
    int lrow = tid >> 1;
    int lk = (tid & 1) * 16;

    const __nv_bfloat16* srcs[2] = {
        g_znh + (size_t)bi * TILE * KDIM, g_enh + (size_t)bj * TILE * KDIM };

    unsigned sm_row = (unsigned)((lrow * AST + lk) * 2);
    unsigned sbase = (unsigned)__cvta_generic_to_shared(csm);

    {
        size_t goff = (size_t)lrow * KDIM + lk;
        #pragma unroll
        for (int a = 0; a < 2; a++) {
            unsigned sa = sbase + a * BUFB + sm_row;
            CP16(sa,      srcs[a] + goff);
            CP16(sa + 16, srcs[a] + goff + 8);
        }
        CP_COMMIT();
    }

    float acc[4][4][4];
    #pragma unroll
    for (int ma = 0; ma < 4; ma++)
        #pragma unroll
        for (int nb = 0; nb < 4; nb++)
            #pragma unroll
            for (int q = 0; q < 4; q++) acc[ma][nb][q] = 0.f;

    for (int q = 0; q < 8; q++) {
        CP_WAIT0();
        __syncthreads();
        if (q < 7) {
            size_t goff = (size_t)lrow * KDIM + (q + 1) * 32 + lk;
            unsigned boff = ((q + 1) & 1) * 2 * BUFB;
            #pragma unroll
            for (int a = 0; a < 2; a++) {
                unsigned sa = sbase + boff + a * BUFB + sm_row;
                CP16(sa,      srcs[a] + goff);
                CP16(sa + 16, srcs[a] + goff + 8);
            }
            CP_COMMIT();
        }
        unsigned bb = sbase + (q & 1) * 2 * BUFB;
        mma_chunk_bf16(bb, bb + BUFB, acc, wm, wn, lane);
    }

    #pragma unroll
    for (int ma = 0; ma < 4; ma++) {
        size_t r0 = (size_t)bi * TILE + wm + ma * 16 + g;
        #pragma unroll
        for (int h = 0; h < 2; h++) {
            size_t rr = r0 + h * 8;
            float m = -2.0f;
            #pragma unroll
            for (int nb = 0; nb < 4; nb++) {
                size_t c = (size_t)bj * TILE + wn + nb * 8 + 2 * t;
                unsigned lo = (unsigned)__bfloat16_as_ushort(
                    __float2bfloat16(acc[ma][nb][h * 2 + 0]));
                unsigned hi = (unsigned)__bfloat16_as_ushort(
                    __float2bfloat16(acc[ma][nb][h * 2 + 1]));
                *(unsigned*)(g_cosb + rr * V + c) = lo | (hi << 16);
                m = fmaxf(m, __uint_as_float(lo << 16));
                m = fmaxf(m, __uint_as_float(hi << 16));
            }
            #pragma unroll
            for (int off = 2; off; off >>= 1)
                m = fmaxf(m, __shfl_xor_sync(0xffffffffu, m, off, 4));
            if (t == 0)
                atomicMax(&g_rowmax[rr], fenc(m));
        }
    }
}

// ---------------------------------------------------------------------------
// Rescore: vectorized gather (threshold from g_rowmax), then WARP-PARALLEL
// exact dots (lane 0 sequential fmaf chain, k ascending). All vector-cast
// shared arrays are 16B-aligned (fixes R14 misaligned-address trap).
// ---------------------------------------------------------------------------
__global__ void __launch_bounds__(256) rescore_kernel(float* __restrict__ out,
                                                      int N, int V) {
    int row = blockIdx.x;
    int tid = threadIdx.x;
    int wid = tid >> 5, lane = tid & 31;
    const uint4* crow = (const uint4*)(g_cosb + (size_t)row * V);  // 8 bf16 each

    __shared__ int   s_cnt;
    __shared__ int   s_cand[MAXCAND];
    __shared__ __align__(16) float s_z[KDIM];
    __shared__ __align__(16) float s_ew[8][KDIM];
    __shared__ float s_bv[8];
    __shared__ int   s_bc[8];

    s_z[tid] = g_znf[(size_t)row * KDIM + tid];
    if (tid == 0) s_cnt = 0;
    __syncthreads();

    float thr = fdec(g_rowmax[row]) - MARGIN;

    // scan: both vectors loaded upfront (MLP=2)
    uint4 w0 = crow[tid];
    uint4 w1 = crow[tid + 256];
    #pragma unroll
    for (int half = 0; half < 2; half++) {
        uint4 w = half ? w1 : w0;
        unsigned u[4] = {w.x, w.y, w.z, w.w};
        int cbase = (tid + half * 256) * 8;
        #pragma unroll
        for (int j = 0; j < 4; j++) {
            float v0 = __uint_as_float(u[j] << 16);
            float v1 = __uint_as_float(u[j] & 0xFFFF0000u);
            if (v0 >= thr) {
                int pos = atomicAdd(&s_cnt, 1);
                if (pos < MAXCAND) s_cand[pos] = cbase + 2 * j;
            }
            if (v1 >= thr) {
                int pos = atomicAdd(&s_cnt, 1);
                if (pos < MAXCAND) s_cand[pos] = cbase + 2 * j + 1;
            }
        }
    }
    __syncthreads();
    int nc = min(s_cnt, MAXCAND);

    // warp-parallel exact dots
    float bv = -4.0f;
    int   bc = 0x7fffffff;
    for (int i = wid; i < nc; i += 8) {
        int c = s_cand[i];
        const float4* e = (const float4*)(g_enf + (size_t)c * KDIM);
        ((float4*)s_ew[wid])[lane]      = e[lane];
        ((float4*)s_ew[wid])[lane + 32] = e[lane + 32];
        __syncwarp();
        if (lane == 0) {
            float d = 0.f;
            #pragma unroll 8
            for (int k = 0; k < KDIM; k++) d = fmaf(s_z[k], s_ew[wid][k], d);
            if (d > bv || (d == bv && c < bc)) { bv = d; bc = c; }
        }
        __syncwarp();
    }
    if (lane == 0) { s_bv[wid] = bv; s_bc[wid] = bc; }
    __syncthreads();

    if (tid == 0) {
        float fbv = -4.0f;
        int   fbc = 0x7fffffff;
        #pragma unroll
        for (int w = 0; w < 8; w++) {
            float d = s_bv[w];
            int   c = s_bc[w];
            if (d > fbv || (d == fbv && c < fbc)) { fbv = d; fbc = c; }
        }
        out[(size_t)N * (size_t)N + row] = (float)fbc;
    }
}

// ---------------------------------------------------------------------------
extern "C" void kernel_launch(void* const* d_in, const int* in_sizes, int n_in,
                              void* d_out, int out_size) {
    const float* z = (const float*)d_in[0];
    const float* e = (const float*)d_in[1];
    float* out = (float*)d_out;

    int N = in_sizes[0] / KDIM;   // 8192
    int V = in_sizes[1] / KDIM;   // 4096
    int T = N / TILE;             // 64

    cudaFuncSetAttribute(adj_sym_kernel,
                         cudaFuncAttributeMaxDynamicSharedMemorySize, ADJ_SMEM);

    prep_kernel<<<N + V, 256>>>(z, e, N, V);

    int nTiles = T * (T + 1) / 2; // 2080
    adj_sym_kernel<<<nTiles, 256, ADJ_SMEM>>>(out, N);

    dim3 gCos(V / TILE, N / TILE);
    cos_kernel<<<gCos, 256>>>(N, V);

    rescore_kernel<<<N, 256>>>(out, N, V);
}

// round 16
// speedup vs baseline: 1.5504x; 1.0259x over previous
#include <cuda_runtime.h>
#include <cuda_bf16.h>
#include <cuda_fp16.h>
#include <math.h>

// z [8192,256] f32, embedding [4096,256] f32.
// out = [ sigmoid(z z^T) (8192x8192 f32) , argmax cosine indices (8192 f32) ]
// adj: fp16 1-term mma.sync + ldmatrix fragments, FMA sigmoid, sym tiles.
// cos: bf16 1-term mma.sync + ldmatrix -> bf16 matrix + fused row-max.
// rescore: vectorized gather + warp-parallel exact sequential-fmaf dots.
// Graph topology: rescore forked onto a side stream, overlapping adj.
// NOTE: tcgen05 unavailable (harness targets compute_103 without 'a').

#define KDIM 256
#define TILE 128
#define NMAX 8192
#define VMAX 4096
#define AST  40          // smem row stride in elements (80B rows, LDSM conflict-free)
#define SST  132         // mirror-staging row stride in f32
#define MARGIN 1.0e-2f   // > bf16-gemm err (3.9e-3) + bf16-store err (2e-3)
#define MAXCAND 256
#define BUFB (TILE * AST * 2)   // 10240 bytes per operand buffer

__device__ __half g_zh [NMAX * KDIM];
__device__ __nv_bfloat16 g_znh[NMAX * KDIM];
__device__ __nv_bfloat16 g_enh[VMAX * KDIM];
__device__ float g_znf[NMAX * KDIM];
__device__ float g_enf[VMAX * KDIM];
__device__ __nv_bfloat16 g_cosb[(size_t)NMAX * VMAX];
__device__ unsigned g_rowmax[NMAX];   // order-preserving float encoding

// ---------------- order-preserving float <-> uint ---------------------------
__device__ __forceinline__ unsigned fenc(float f) {
    unsigned b = __float_as_uint(f);
    return (b & 0x80000000u) ? ~b : (b | 0x80000000u);
}
__device__ __forceinline__ float fdec(unsigned u) {
    return (u & 0x80000000u) ? __uint_as_float(u & 0x7FFFFFFFu)
                             : __uint_as_float(~u);
}

// ---------------- cp.async helpers ------------------------------------------
#define CP16(sa, gp) \
    asm volatile("cp.async.cg.shared.global [%0], [%1], 16;" \
                 :: "r"(sa), "l"(gp) : "memory")
#define CP_COMMIT() asm volatile("cp.async.commit_group;" ::: "memory")
#define CP_WAIT0()  asm volatile("cp.async.wait_group 0;" ::: "memory")

// ===================== FMA-only sigmoid (no MUFU) ===========================
__device__ __forceinline__ float sigmoid_fast(float x) {
    float ax = fminf(fabsf(x), 30.0f);
    float u  = ax * 1.4426950408889634f;
    float fm = u + 12582912.0f;
    float n  = fm - 12582912.0f;
    float f  = n - u;
    float p  = 1.3333558146428443e-3f;
    p = fmaf(p, f, 9.6181291976353954e-3f);
    p = fmaf(p, f, 5.5504108664798463e-2f);
    p = fmaf(p, f, 2.4022650695910071e-1f);
    p = fmaf(p, f, 6.9314718055994531e-1f);
    p = fmaf(p, f, 1.0f);
    int nbits = (__float_as_int(fm) & 0x7F) << 23;
    float scale = __int_as_float(0x3F800000 - nbits);
    float q = p * scale;
    float d = 1.0f + q;
    float r = fmaf(d, fmaf(d, 0.33333333f, -1.5f), 2.16666667f);
    r = r * (2.0f - d * r);
    r = r * (2.0f - d * r);
    return (x >= 0.0f) ? r : r * q;
}

// ===================== prep: normalize + splits =============================
__global__ void prep_kernel(const float* __restrict__ z,
                            const float* __restrict__ e,
                            int N, int V) {
    int row = blockIdx.x;
    int tid = threadIdx.x;
    bool isZ = row < N;
    const float* src = isZ ? (z + (size_t)row * KDIM)
                           : (e + (size_t)(row - N) * KDIM);
    float v = src[tid];

    float ss = v * v;
    #pragma unroll
    for (int o = 16; o; o >>= 1) ss += __shfl_xor_sync(0xffffffffu, ss, o);
    __shared__ float s_partial[8];
    __shared__ float s_total;
    if ((tid & 31) == 0) s_partial[tid >> 5] = ss;
    __syncthreads();
    if (tid == 0) {
        float t = 0.f;
        #pragma unroll
        for (int i = 0; i < 8; i++) t += s_partial[i];
        s_total = t;
    }
    __syncthreads();
    float inv = 1.0f / fmaxf(sqrtf(s_total), 1e-8f);
    float vn = v * inv;

    if (isZ) {
        size_t o = (size_t)row * KDIM + tid;
        g_zh[o] = __float2half_rn(v);
        g_znh[o] = __float2bfloat16(vn);
        g_znf[o] = vn;
        if (tid == 0) g_rowmax[row] = 0u;   // reset per launch
    } else {
        size_t o = (size_t)(row - N) * KDIM + tid;
        g_enh[o] = __float2bfloat16(vn);
        g_enf[o] = vn;
    }
}

// ---------------------------------------------------------------------------
__device__ __forceinline__ void mma_f16(float c[4], const unsigned a[4],
                                        const unsigned b[2]) {
    asm volatile(
        "mma.sync.aligned.m16n8k16.row.col.f32.f16.f16.f32 "
        "{%0,%1,%2,%3}, {%4,%5,%6,%7}, {%8,%9}, {%0,%1,%2,%3};"
        : "+f"(c[0]), "+f"(c[1]), "+f"(c[2]), "+f"(c[3])
        : "r"(a[0]), "r"(a[1]), "r"(a[2]), "r"(a[3]), "r"(b[0]), "r"(b[1]));
}
__device__ __forceinline__ void mma_bf16(float c[4], const unsigned a[4],
                                         const unsigned b[2]) {
    asm volatile(
        "mma.sync.aligned.m16n8k16.row.col.f32.bf16.bf16.f32 "
        "{%0,%1,%2,%3}, {%4,%5,%6,%7}, {%8,%9}, {%0,%1,%2,%3};"
        : "+f"(c[0]), "+f"(c[1]), "+f"(c[2]), "+f"(c[3])
        : "r"(a[0]), "r"(a[1]), "r"(a[2]), "r"(a[3]), "r"(b[0]), "r"(b[1]));
}
__device__ __forceinline__ void ldsm_x4(unsigned& d0, unsigned& d1,
                                        unsigned& d2, unsigned& d3,
                                        unsigned addr) {
    asm volatile("ldmatrix.sync.aligned.m8n8.x4.shared.b16 {%0,%1,%2,%3}, [%4];"
                 : "=r"(d0), "=r"(d1), "=r"(d2), "=r"(d3) : "r"(addr));
}

// Fragment load via ldmatrix for one 32-k chunk; smem [128][AST] b16.
__device__ __forceinline__ void load_frags(unsigned sbA, unsigned sbB,
                                           unsigned ah[4][4], unsigned bh[4][2],
                                           int wm, int wn, int lane, int k0) {
    int arow = lane & 15;
    int akoff = k0 + (lane >> 4) * 8;
    #pragma unroll
    for (int ma = 0; ma < 4; ma++) {
        unsigned addr = sbA + (unsigned)(((wm + ma * 16 + arow) * AST + akoff) * 2);
        ldsm_x4(ah[ma][0], ah[ma][1], ah[ma][2], ah[ma][3], addr);
    }
    int bcol = (lane & 7) + ((lane >> 4) << 3);
    int bkoff = k0 + ((lane >> 3) & 1) * 8;
    #pragma unroll
    for (int nbp = 0; nbp < 2; nbp++) {
        unsigned addr = sbB + (unsigned)(((wn + nbp * 16 + bcol) * AST + bkoff) * 2);
        unsigned d0, d1, d2, d3;
        ldsm_x4(d0, d1, d2, d3, addr);
        bh[nbp * 2][0] = d0;     bh[nbp * 2][1] = d1;
        bh[nbp * 2 + 1][0] = d2; bh[nbp * 2 + 1][1] = d3;
    }
}

__device__ __forceinline__ void mma_chunk_f16(unsigned sbA, unsigned sbB,
                                              float acc[4][4][4],
                                              int wm, int wn, int lane) {
    #pragma unroll
    for (int ks = 0; ks < 2; ks++) {
        unsigned ah[4][4], bh[4][2];
        load_frags(sbA, sbB, ah, bh, wm, wn, lane, ks * 16);
        #pragma unroll
        for (int ma = 0; ma < 4; ma++)
            #pragma unroll
            for (int nb = 0; nb < 4; nb++)
                mma_f16(acc[ma][nb], ah[ma], bh[nb]);
    }
}
__device__ __forceinline__ void mma_chunk_bf16(unsigned sbA, unsigned sbB,
                                               float acc[4][4][4],
                                               int wm, int wn, int lane) {
    #pragma unroll
    for (int ks = 0; ks < 2; ks++) {
        unsigned ah[4][4], bh[4][2];
        load_frags(sbA, sbB, ah, bh, wm, wn, lane, ks * 16);
        #pragma unroll
        for (int ma = 0; ma < 4; ma++)
            #pragma unroll
            for (int nb = 0; nb < 4; nb++)
                mma_bf16(acc[ma][nb], ah[ma], bh[nb]);
    }
}

// ---------------------------------------------------------------------------
// adj: upper-tri tiles, fp16 1-term, cp.async double buffer, mirror writes.
// ---------------------------------------------------------------------------
#define ADJ_SMEM (2 * 2 * BUFB)

__global__ void __launch_bounds__(256) adj_sym_kernel(float* __restrict__ out, int N) {
    extern __shared__ __align__(16) unsigned char dsm[];
    float (*S)[SST] = (float(*)[SST])dsm;

    const int T = N / TILE;
    int tt = blockIdx.x;
    int bi = 0;
    while (tt >= (T - bi)) { tt -= (T - bi); bi++; }
    int bj = bi + tt;

    int tid = threadIdx.x;
    int warp = tid >> 5, lane = tid & 31;
    int g = lane >> 2, t = lane & 3;
    int wm = (warp >> 2) * 64;
    int wn = (warp & 3) * 32;
    int lrow = tid >> 1;
    int lk = (tid & 1) * 16;

    const __half* srcs[2] = {
        g_zh + (size_t)bi * TILE * KDIM,
        g_zh + (size_t)bj * TILE * KDIM };

    unsigned sm_row = (unsigned)((lrow * AST + lk) * 2);
    unsigned sbase = (unsigned)__cvta_generic_to_shared(dsm);

    {
        size_t goff = (size_t)lrow * KDIM + lk;
        #pragma unroll
        for (int a = 0; a < 2; a++) {
            unsigned sa = sbase + a * BUFB + sm_row;
            CP16(sa,      srcs[a] + goff);
            CP16(sa + 16, srcs[a] + goff + 8);
        }
        CP_COMMIT();
    }

    float acc[4][4][4];
    #pragma unroll
    for (int ma = 0; ma < 4; ma++)
        #pragma unroll
        for (int nb = 0; nb < 4; nb++)
            #pragma unroll
            for (int q = 0; q < 4; q++) acc[ma][nb][q] = 0.f;

    for (int q = 0; q < 8; q++) {
        CP_WAIT0();
        __syncthreads();
        if (q < 7) {
            size_t goff = (size_t)lrow * KDIM + (q + 1) * 32 + lk;
            unsigned boff = ((q + 1) & 1) * 2 * BUFB;
            #pragma unroll
            for (int a = 0; a < 2; a++) {
                unsigned sa = sbase + boff + a * BUFB + sm_row;
                CP16(sa,      srcs[a] + goff);
                CP16(sa + 16, srcs[a] + goff + 8);
            }
            CP_COMMIT();
        }
        unsigned bb = sbase + (q & 1) * 2 * BUFB;
        mma_chunk_f16(bb, bb + BUFB, acc, wm, wn, lane);
    }

    #pragma unroll
    for (int ma = 0; ma < 4; ma++)
        #pragma unroll
        for (int nb = 0; nb < 4; nb++)
            #pragma unroll
            for (int q = 0; q < 4; q++)
                acc[ma][nb][q] = sigmoid_fast(acc[ma][nb][q]);

    #pragma unroll
    for (int ma = 0; ma < 4; ma++) {
        size_t r0 = (size_t)bi * TILE + wm + ma * 16 + g;
        #pragma unroll
        for (int nb = 0; nb < 4; nb++) {
            size_t c = (size_t)bj * TILE + wn + nb * 8 + 2 * t;
            *(float2*)(out + r0 * N + c)       = make_float2(acc[ma][nb][0], acc[ma][nb][1]);
            *(float2*)(out + (r0 + 8) * N + c) = make_float2(acc[ma][nb][2], acc[ma][nb][3]);
        }
    }

    if (bi == bj) return;

    int myHalf = (warp & 3) >> 1;
    #pragma unroll
    for (int ch = 0; ch < 2; ch++) {
        __syncthreads();
        if (myHalf == ch) {
            int cl = (warp & 1) * 32;
            #pragma unroll
            for (int ma = 0; ma < 4; ma++) {
                int r = wm + ma * 16 + g;
                #pragma unroll
                for (int nb = 0; nb < 4; nb++) {
                    int c = cl + nb * 8 + 2 * t;
                    S[c][r]         = acc[ma][nb][0];
                    S[c + 1][r]     = acc[ma][nb][1];
                    S[c][r + 8]     = acc[ma][nb][2];
                    S[c + 1][r + 8] = acc[ma][nb][3];
                }
            }
        }
        __syncthreads();
        #pragma unroll
        for (int q = 0; q < 8; q++) {
            int idx = tid + 256 * q;
            int mr = idx >> 5;
            int fc = idx & 31;
            size_t grow = (size_t)bj * TILE + ch * 64 + mr;
            *(float4*)(out + grow * N + (size_t)bi * TILE + fc * 4) =
                *(const float4*)&S[mr][fc * 4];
        }
    }
}

// ---------------------------------------------------------------------------
// cos: 1-term bf16 GEMM (ldmatrix) -> bf16 matrix + fused per-row atomic max.
// ---------------------------------------------------------------------------
__global__ void __launch_bounds__(256) cos_kernel(int N, int V) {
    __shared__ __align__(16) unsigned char csm[2 * 2 * BUFB];

    int tid = threadIdx.x;
    int warp = tid >> 5, lane = tid & 31;
    int g = lane >> 2, t = lane & 3;
    int wm = (warp >> 2) * 64;
    int wn = (warp & 3) * 32;
    int bi = blockIdx.y;
    int bj = blockIdx.x;
    int lrow = tid >> 1;
    int lk = (tid & 1) * 16;

    const __nv_bfloat16* srcs[2] = {
        g_znh + (size_t)bi * TILE * KDIM, g_enh + (size_t)bj * TILE * KDIM };

    unsigned sm_row = (unsigned)((lrow * AST + lk) * 2);
    unsigned sbase = (unsigned)__cvta_generic_to_shared(csm);

    {
        size_t goff = (size_t)lrow * KDIM + lk;
        #pragma unroll
        for (int a = 0; a < 2; a++) {
            unsigned sa = sbase + a * BUFB + sm_row;
            CP16(sa,      srcs[a] + goff);
            CP16(sa + 16, srcs[a] + goff + 8);
        }
        CP_COMMIT();
    }

    float acc[4][4][4];
    #pragma unroll
    for (int ma = 0; ma < 4; ma++)
        #pragma unroll
        for (int nb = 0; nb < 4; nb++)
            #pragma unroll
            for (int q = 0; q < 4; q++) acc[ma][nb][q] = 0.f;

    for (int q = 0; q < 8; q++) {
        CP_WAIT0();
        __syncthreads();
        if (q < 7) {
            size_t goff = (size_t)lrow * KDIM + (q + 1) * 32 + lk;
            unsigned boff = ((q + 1) & 1) * 2 * BUFB;
            #pragma unroll
            for (int a = 0; a < 2; a++) {
                unsigned sa = sbase + boff + a * BUFB + sm_row;
                CP16(sa,      srcs[a] + goff);
                CP16(sa + 16, srcs[a] + goff + 8);
            }
            CP_COMMIT();
        }
        unsigned bb = sbase + (q & 1) * 2 * BUFB;
        mma_chunk_bf16(bb, bb + BUFB, acc, wm, wn, lane);
    }

    #pragma unroll
    for (int ma = 0; ma < 4; ma++) {
        size_t r0 = (size_t)bi * TILE + wm + ma * 16 + g;
        #pragma unroll
        for (int h = 0; h < 2; h++) {
            size_t rr = r0 + h * 8;
            float m = -2.0f;
            #pragma unroll
            for (int nb = 0; nb < 4; nb++) {
                size_t c = (size_t)bj * TILE + wn + nb * 8 + 2 * t;
                unsigned lo = (unsigned)__bfloat16_as_ushort(
                    __float2bfloat16(acc[ma][nb][h * 2 + 0]));
                unsigned hi = (unsigned)__bfloat16_as_ushort(
                    __float2bfloat16(acc[ma][nb][h * 2 + 1]));
                *(unsigned*)(g_cosb + rr * V + c) = lo | (hi << 16);
                m = fmaxf(m, __uint_as_float(lo << 16));
                m = fmaxf(m, __uint_as_float(hi << 16));
            }
            #pragma unroll
            for (int off = 2; off; off >>= 1)
                m = fmaxf(m, __shfl_xor_sync(0xffffffffu, m, off, 4));
            if (t == 0)
                atomicMax(&g_rowmax[rr], fenc(m));
        }
    }
}

// ---------------------------------------------------------------------------
// Rescore: vectorized gather + warp-parallel exact sequential-fmaf dots.
// ---------------------------------------------------------------------------
__global__ void __launch_bounds__(256) rescore_kernel(float* __restrict__ out,
                                                      int N, int V) {
    int row = blockIdx.x;
    int tid = threadIdx.x;
    int wid = tid >> 5, lane = tid & 31;
    const uint4* crow = (const uint4*)(g_cosb + (size_t)row * V);  // 8 bf16 each

    __shared__ int   s_cnt;
    __shared__ int   s_cand[MAXCAND];
    __shared__ __align__(16) float s_z[KDIM];
    __shared__ __align__(16) float s_ew[8][KDIM];
    __shared__ float s_bv[8];
    __shared__ int   s_bc[8];

    s_z[tid] = g_znf[(size_t)row * KDIM + tid];
    if (tid == 0) s_cnt = 0;
    __syncthreads();

    float thr = fdec(g_rowmax[row]) - MARGIN;

    uint4 w0 = crow[tid];
    uint4 w1 = crow[tid + 256];
    #pragma unroll
    for (int half = 0; half < 2; half++) {
        uint4 w = half ? w1 : w0;
        unsigned u[4] = {w.x, w.y, w.z, w.w};
        int cbase = (tid + half * 256) * 8;
        #pragma unroll
        for (int j = 0; j < 4; j++) {
            float v0 = __uint_as_float(u[j] << 16);
            float v1 = __uint_as_float(u[j] & 0xFFFF0000u);
            if (v0 >= thr) {
                int pos = atomicAdd(&s_cnt, 1);
                if (pos < MAXCAND) s_cand[pos] = cbase + 2 * j;
            }
            if (v1 >= thr) {
                int pos = atomicAdd(&s_cnt, 1);
                if (pos < MAXCAND) s_cand[pos] = cbase + 2 * j + 1;
            }
        }
    }
    __syncthreads();
    int nc = min(s_cnt, MAXCAND);

    float bv = -4.0f;
    int   bc = 0x7fffffff;
    for (int i = wid; i < nc; i += 8) {
        int c = s_cand[i];
        const float4* e = (const float4*)(g_enf + (size_t)c * KDIM);
        ((float4*)s_ew[wid])[lane]      = e[lane];
        ((float4*)s_ew[wid])[lane + 32] = e[lane + 32];
        __syncwarp();
        if (lane == 0) {
            float d = 0.f;
            #pragma unroll 8
            for (int k = 0; k < KDIM; k++) d = fmaf(s_z[k], s_ew[wid][k], d);
            if (d > bv || (d == bv && c < bc)) { bv = d; bc = c; }
        }
        __syncwarp();
    }
    if (lane == 0) { s_bv[wid] = bv; s_bc[wid] = bc; }
    __syncthreads();

    if (tid == 0) {
        float fbv = -4.0f;
        int   fbc = 0x7fffffff;
        #pragma unroll
        for (int w = 0; w < 8; w++) {
            float d = s_bv[w];
            int   c = s_bc[w];
            if (d > fbv || (d == fbv && c < fbc)) { fbv = d; fbc = c; }
        }
        out[(size_t)N * (size_t)N + row] = (float)fbc;
    }
}

// ---------------------------------------------------------------------------
// Launch: fork rescore onto a side stream so it overlaps adj.
//   main: prep -> cos -> [evCos] -> adj -> wait(evDone)
//   side:         wait(evCos) -> rescore -> [evDone]
// Streams/events are created per call (capture-legal; no device memory).
// ---------------------------------------------------------------------------
extern "C" void kernel_launch(void* const* d_in, const int* in_sizes, int n_in,
                              void* d_out, int out_size) {
    const float* z = (const float*)d_in[0];
    const float* e = (const float*)d_in[1];
    float* out = (float*)d_out;

    int N = in_sizes[0] / KDIM;   // 8192
    int V = in_sizes[1] / KDIM;   // 4096
    int T = N / TILE;             // 64

    cudaFuncSetAttribute(adj_sym_kernel,
                         cudaFuncAttributeMaxDynamicSharedMemorySize, ADJ_SMEM);

    cudaStream_t side;
    cudaStreamCreateWithFlags(&side, cudaStreamNonBlocking);
    cudaEvent_t evCos, evDone;
    cudaEventCreateWithFlags(&evCos, cudaEventDisableTiming);
    cudaEventCreateWithFlags(&evDone, cudaEventDisableTiming);

    prep_kernel<<<N + V, 256>>>(z, e, N, V);

    dim3 gCos(V / TILE, N / TILE);
    cos_kernel<<<gCos, 256>>>(N, V);
    cudaEventRecord(evCos, 0);

    cudaStreamWaitEvent(side, evCos, 0);
    rescore_kernel<<<N, 256, 0, side>>>(out, N, V);
    cudaEventRecord(evDone, side);

    int nTiles = T * (T + 1) / 2; // 2080
    adj_sym_kernel<<<nTiles, 256, ADJ_SMEM>>>(out, N);

    cudaStreamWaitEvent(0, evDone, 0);
}

// round 17
// speedup vs baseline: 1.5704x; 1.0129x over previous
#include <cuda_runtime.h>
#include <cuda_bf16.h>
#include <cuda_fp16.h>
#include <math.h>

// z [8192,256] f32, embedding [4096,256] f32.
// out = [ sigmoid(z z^T) (8192x8192 f32) , argmax cosine indices (8192 f32) ]
// adj: fp16 1-term mma.sync + ldmatrix fragments, FMA sigmoid, sym tiles.
// cos: bf16 1-term mma.sync + ldmatrix -> bf16 matrix + fused row-max.
// rescore: vectorized gather + warp-parallel exact sequential-fmaf dots.
// Topology: adj runs CONCURRENTLY with (cos -> rescore) — each GEMM alone
// leaves the tensor pipe ~75% idle (R16 profile), so overlap fills it.
// NOTE: tcgen05 unavailable (harness targets compute_103 without 'a').

#define KDIM 256
#define TILE 128
#define NMAX 8192
#define VMAX 4096
#define AST  40          // smem row stride in elements (80B rows, LDSM conflict-free)
#define SST  132         // mirror-staging row stride in f32
#define MARGIN 1.0e-2f   // > bf16-gemm err (3.9e-3) + bf16-store err (2e-3)
#define MAXCAND 256
#define BUFB (TILE * AST * 2)   // 10240 bytes per operand buffer

__device__ __half g_zh [NMAX * KDIM];
__device__ __nv_bfloat16 g_znh[NMAX * KDIM];
__device__ __nv_bfloat16 g_enh[VMAX * KDIM];
__device__ float g_znf[NMAX * KDIM];
__device__ float g_enf[VMAX * KDIM];
__device__ __nv_bfloat16 g_cosb[(size_t)NMAX * VMAX];
__device__ unsigned g_rowmax[NMAX];   // order-preserving float encoding

// ---------------- order-preserving float <-> uint ---------------------------
__device__ __forceinline__ unsigned fenc(float f) {
    unsigned b = __float_as_uint(f);
    return (b & 0x80000000u) ? ~b : (b | 0x80000000u);
}
__device__ __forceinline__ float fdec(unsigned u) {
    return (u & 0x80000000u) ? __uint_as_float(u & 0x7FFFFFFFu)
                             : __uint_as_float(~u);
}

// ---------------- cp.async helpers ------------------------------------------
#define CP16(sa, gp) \
    asm volatile("cp.async.cg.shared.global [%0], [%1], 16;" \
                 :: "r"(sa), "l"(gp) : "memory")
#define CP_COMMIT() asm volatile("cp.async.commit_group;" ::: "memory")
#define CP_WAIT0()  asm volatile("cp.async.wait_group 0;" ::: "memory")

// ===================== FMA-only sigmoid (no MUFU) ===========================
__device__ __forceinline__ float sigmoid_fast(float x) {
    float ax = fminf(fabsf(x), 30.0f);
    float u  = ax * 1.4426950408889634f;
    float fm = u + 12582912.0f;
    float n  = fm - 12582912.0f;
    float f  = n - u;
    float p  = 1.3333558146428443e-3f;
    p = fmaf(p, f, 9.6181291976353954e-3f);
    p = fmaf(p, f, 5.5504108664798463e-2f);
    p = fmaf(p, f, 2.4022650695910071e-1f);
    p = fmaf(p, f, 6.9314718055994531e-1f);
    p = fmaf(p, f, 1.0f);
    int nbits = (__float_as_int(fm) & 0x7F) << 23;
    float scale = __int_as_float(0x3F800000 - nbits);
    float q = p * scale;
    float d = 1.0f + q;
    float r = fmaf(d, fmaf(d, 0.33333333f, -1.5f), 2.16666667f);
    r = r * (2.0f - d * r);
    r = r * (2.0f - d * r);
    return (x >= 0.0f) ? r : r * q;
}

// ===================== prep: normalize + splits =============================
__global__ void prep_kernel(const float* __restrict__ z,
                            const float* __restrict__ e,
                            int N, int V) {
    int row = blockIdx.x;
    int tid = threadIdx.x;
    bool isZ = row < N;
    const float* src = isZ ? (z + (size_t)row * KDIM)
                           : (e + (size_t)(row - N) * KDIM);
    float v = src[tid];

    float ss = v * v;
    #pragma unroll
    for (int o = 16; o; o >>= 1) ss += __shfl_xor_sync(0xffffffffu, ss, o);
    __shared__ float s_partial[8];
    __shared__ float s_total;
    if ((tid & 31) == 0) s_partial[tid >> 5] = ss;
    __syncthreads();
    if (tid == 0) {
        float t = 0.f;
        #pragma unroll
        for (int i = 0; i < 8; i++) t += s_partial[i];
        s_total = t;
    }
    __syncthreads();
    float inv = 1.0f / fmaxf(sqrtf(s_total), 1e-8f);
    float vn = v * inv;

    if (isZ) {
        size_t o = (size_t)row * KDIM + tid;
        g_zh[o] = __float2half_rn(v);
        g_znh[o] = __float2bfloat16(vn);
        g_znf[o] = vn;
        if (tid == 0) g_rowmax[row] = 0u;   // reset per launch
    } else {
        size_t o = (size_t)(row - N) * KDIM + tid;
        g_enh[o] = __float2bfloat16(vn);
        g_enf[o] = vn;
    }
}

// ---------------------------------------------------------------------------
__device__ __forceinline__ void mma_f16(float c[4], const unsigned a[4],
                                        const unsigned b[2]) {
    asm volatile(
        "mma.sync.aligned.m16n8k16.row.col.f32.f16.f16.f32 "
        "{%0,%1,%2,%3}, {%4,%5,%6,%7}, {%8,%9}, {%0,%1,%2,%3};"
        : "+f"(c[0]), "+f"(c[1]), "+f"(c[2]), "+f"(c[3])
        : "r"(a[0]), "r"(a[1]), "r"(a[2]), "r"(a[3]), "r"(b[0]), "r"(b[1]));
}
__device__ __forceinline__ void mma_bf16(float c[4], const unsigned a[4],
                                         const unsigned b[2]) {
    asm volatile(
        "mma.sync.aligned.m16n8k16.row.col.f32.bf16.bf16.f32 "
        "{%0,%1,%2,%3}, {%4,%5,%6,%7}, {%8,%9}, {%0,%1,%2,%3};"
        : "+f"(c[0]), "+f"(c[1]), "+f"(c[2]), "+f"(c[3])
        : "r"(a[0]), "r"(a[1]), "r"(a[2]), "r"(a[3]), "r"(b[0]), "r"(b[1]));
}
__device__ __forceinline__ void ldsm_x4(unsigned& d0, unsigned& d1,
                                        unsigned& d2, unsigned& d3,
                                        unsigned addr) {
    asm volatile("ldmatrix.sync.aligned.m8n8.x4.shared.b16 {%0,%1,%2,%3}, [%4];"
                 : "=r"(d0), "=r"(d1), "=r"(d2), "=r"(d3) : "r"(addr));
}

// Fragment load via ldmatrix for one 32-k chunk; smem [128][AST] b16.
__device__ __forceinline__ void load_frags(unsigned sbA, unsigned sbB,
                                           unsigned ah[4][4], unsigned bh[4][2],
                                           int wm, int wn, int lane, int k0) {
    int arow = lane & 15;
    int akoff = k0 + (lane >> 4) * 8;
    #pragma unroll
    for (int ma = 0; ma < 4; ma++) {
        unsigned addr = sbA + (unsigned)(((wm + ma * 16 + arow) * AST + akoff) * 2);
        ldsm_x4(ah[ma][0], ah[ma][1], ah[ma][2], ah[ma][3], addr);
    }
    int bcol = (lane & 7) + ((lane >> 4) << 3);
    int bkoff = k0 + ((lane >> 3) & 1) * 8;
    #pragma unroll
    for (int nbp = 0; nbp < 2; nbp++) {
        unsigned addr = sbB + (unsigned)(((wn + nbp * 16 + bcol) * AST + bkoff) * 2);
        unsigned d0, d1, d2, d3;
        ldsm_x4(d0, d1, d2, d3, addr);
        bh[nbp * 2][0] = d0;     bh[nbp * 2][1] = d1;
        bh[nbp * 2 + 1][0] = d2; bh[nbp * 2 + 1][1] = d3;
    }
}

__device__ __forceinline__ void mma_chunk_f16(unsigned sbA, unsigned sbB,
                                              float acc[4][4][4],
                                              int wm, int wn, int lane) {
    #pragma unroll
    for (int ks = 0; ks < 2; ks++) {
        unsigned ah[4][4], bh[4][2];
        load_frags(sbA, sbB, ah, bh, wm, wn, lane, ks * 16);
        #pragma unroll
        for (int ma = 0; ma < 4; ma++)
            #pragma unroll
            for (int nb = 0; nb < 4; nb++)
                mma_f16(acc[ma][nb], ah[ma], bh[nb]);
    }
}
__device__ __forceinline__ void mma_chunk_bf16(unsigned sbA, unsigned sbB,
                                               float acc[4][4][4],
                                               int wm, int wn, int lane) {
    #pragma unroll
    for (int ks = 0; ks < 2; ks++) {
        unsigned ah[4][4], bh[4][2];
        load_frags(sbA, sbB, ah, bh, wm, wn, lane, ks * 16);
        #pragma unroll
        for (int ma = 0; ma < 4; ma++)
            #pragma unroll
            for (int nb = 0; nb < 4; nb++)
                mma_bf16(acc[ma][nb], ah[ma], bh[nb]);
    }
}

// ---------------------------------------------------------------------------
// adj: upper-tri tiles, fp16 1-term, cp.async double buffer, mirror writes.
// ---------------------------------------------------------------------------
#define ADJ_SMEM (2 * 2 * BUFB)

__global__ void __launch_bounds__(256) adj_sym_kernel(float* __restrict__ out, int N) {
    extern __shared__ __align__(16) unsigned char dsm[];
    float (*S)[SST] = (float(*)[SST])dsm;

    const int T = N / TILE;
    int tt = blockIdx.x;
    int bi = 0;
    while (tt >= (T - bi)) { tt -= (T - bi); bi++; }
    int bj = bi + tt;

    int tid = threadIdx.x;
    int warp = tid >> 5, lane = tid & 31;
    int g = lane >> 2, t = lane & 3;
    int wm = (warp >> 2) * 64;
    int wn = (warp & 3) * 32;
    int lrow = tid >> 1;
    int lk = (tid & 1) * 16;

    const __half* srcs[2] = {
        g_zh + (size_t)bi * TILE * KDIM,
        g_zh + (size_t)bj * TILE * KDIM };

    unsigned sm_row = (unsigned)((lrow * AST + lk) * 2);
    unsigned sbase = (unsigned)__cvta_generic_to_shared(dsm);

    {
        size_t goff = (size_t)lrow * KDIM + lk;
        #pragma unroll
        for (int a = 0; a < 2; a++) {
            unsigned sa = sbase + a * BUFB + sm_row;
            CP16(sa,      srcs[a] + goff);
            CP16(sa + 16, srcs[a] + goff + 8);
        }
        CP_COMMIT();
    }

    float acc[4][4][4];
    #pragma unroll
    for (int ma = 0; ma < 4; ma++)
        #pragma unroll
        for (int nb = 0; nb < 4; nb++)
            #pragma unroll
            for (int q = 0; q < 4; q++) acc[ma][nb][q] = 0.f;

    for (int q = 0; q < 8; q++) {
        CP_WAIT0();
        __syncthreads();
        if (q < 7) {
            size_t goff = (size_t)lrow * KDIM + (q + 1) * 32 + lk;
            unsigned boff = ((q + 1) & 1) * 2 * BUFB;
            #pragma unroll
            for (int a = 0; a < 2; a++) {
                unsigned sa = sbase + boff + a * BUFB + sm_row;
                CP16(sa,      srcs[a] + goff);
                CP16(sa + 16, srcs[a] + goff + 8);
            }
            CP_COMMIT();
        }
        unsigned bb = sbase + (q & 1) * 2 * BUFB;
        mma_chunk_f16(bb, bb + BUFB, acc, wm, wn, lane);
    }

    #pragma unroll
    for (int ma = 0; ma < 4; ma++)
        #pragma unroll
        for (int nb = 0; nb < 4; nb++)
            #pragma unroll
            for (int q = 0; q < 4; q++)
                acc[ma][nb][q] = sigmoid_fast(acc[ma][nb][q]);

    #pragma unroll
    for (int ma = 0; ma < 4; ma++) {
        size_t r0 = (size_t)bi * TILE + wm + ma * 16 + g;
        #pragma unroll
        for (int nb = 0; nb < 4; nb++) {
            size_t c = (size_t)bj * TILE + wn + nb * 8 + 2 * t;
            *(float2*)(out + r0 * N + c)       = make_float2(acc[ma][nb][0], acc[ma][nb][1]);
            *(float2*)(out + (r0 + 8) * N + c) = make_float2(acc[ma][nb][2], acc[ma][nb][3]);
        }
    }

    if (bi == bj) return;

    int myHalf = (warp & 3) >> 1;
    #pragma unroll
    for (int ch = 0; ch < 2; ch++) {
        __syncthreads();
        if (myHalf == ch) {
            int cl = (warp & 1) * 32;
            #pragma unroll
            for (int ma = 0; ma < 4; ma++) {
                int r = wm + ma * 16 + g;
                #pragma unroll
                for (int nb = 0; nb < 4; nb++) {
                    int c = cl + nb * 8 + 2 * t;
                    S[c][r]         = acc[ma][nb][0];
                    S[c + 1][r]     = acc[ma][nb][1];
                    S[c][r + 8]     = acc[ma][nb][2];
                    S[c + 1][r + 8] = acc[ma][nb][3];
                }
            }
        }
        __syncthreads();
        #pragma unroll
        for (int q = 0; q < 8; q++) {
            int idx = tid + 256 * q;
            int mr = idx >> 5;
            int fc = idx & 31;
            size_t grow = (size_t)bj * TILE + ch * 64 + mr;
            *(float4*)(out + grow * N + (size_t)bi * TILE + fc * 4) =
                *(const float4*)&S[mr][fc * 4];
        }
    }
}

// ---------------------------------------------------------------------------
// cos: 1-term bf16 GEMM (ldmatrix) -> bf16 matrix + fused per-row atomic max.
// ---------------------------------------------------------------------------
__global__ void __launch_bounds__(256) cos_kernel(int N, int V) {
    __shared__ __align__(16) unsigned char csm[2 * 2 * BUFB];

    int tid = threadIdx.x;
    int warp = tid >> 5, lane = tid & 31;
    int g = lane >> 2, t = lane & 3;
    int wm = (warp >> 2) * 64;
    int wn = (warp & 3) * 32;
    int bi = blockIdx.y;
    int bj = blockIdx.x;
    int lrow = tid >> 1;
    int lk = (tid & 1) * 16;

    const __nv_bfloat16* srcs[2] = {
        g_znh + (size_t)bi * TILE * KDIM, g_enh + (size_t)bj * TILE * KDIM };

    unsigned sm_row = (unsigned)((lrow * AST + lk) * 2);
    unsigned sbase = (unsigned)__cvta_generic_to_shared(csm);

    {
        size_t goff = (size_t)lrow * KDIM + lk;
        #pragma unroll
        for (int a = 0; a < 2; a++) {
            unsigned sa = sbase + a * BUFB + sm_row;
            CP16(sa,      srcs[a] + goff);
            CP16(sa + 16, srcs[a] + goff + 8);
        }
        CP_COMMIT();
    }

    float acc[4][4][4];
    #pragma unroll
    for (int ma = 0; ma < 4; ma++)
        #pragma unroll
        for (int nb = 0; nb < 4; nb++)
            #pragma unroll
            for (int q = 0; q < 4; q++) acc[ma][nb][q] = 0.f;

    for (int q = 0; q < 8; q++) {
        CP_WAIT0();
        __syncthreads();
        if (q < 7) {
            size_t goff = (size_t)lrow * KDIM + (q + 1) * 32 + lk;
            unsigned boff = ((q + 1) & 1) * 2 * BUFB;
            #pragma unroll
            for (int a = 0; a < 2; a++) {
                unsigned sa = sbase + boff + a * BUFB + sm_row;
                CP16(sa,      srcs[a] + goff);
                CP16(sa + 16, srcs[a] + goff + 8);
            }
            CP_COMMIT();
        }
        unsigned bb = sbase + (q & 1) * 2 * BUFB;
        mma_chunk_bf16(bb, bb + BUFB, acc, wm, wn, lane);
    }

    #pragma unroll
    for (int ma = 0; ma < 4; ma++) {
        size_t r0 = (size_t)bi * TILE + wm + ma * 16 + g;
        #pragma unroll
        for (int h = 0; h < 2; h++) {
            size_t rr = r0 + h * 8;
            float m = -2.0f;
            #pragma unroll
            for (int nb = 0; nb < 4; nb++) {
                size_t c = (size_t)bj * TILE + wn + nb * 8 + 2 * t;
                unsigned lo = (unsigned)__bfloat16_as_ushort(
                    __float2bfloat16(acc[ma][nb][h * 2 + 0]));
                unsigned hi = (unsigned)__bfloat16_as_ushort(
                    __float2bfloat16(acc[ma][nb][h * 2 + 1]));
                *(unsigned*)(g_cosb + rr * V + c) = lo | (hi << 16);
                m = fmaxf(m, __uint_as_float(lo << 16));
                m = fmaxf(m, __uint_as_float(hi << 16));
            }
            #pragma unroll
            for (int off = 2; off; off >>= 1)
                m = fmaxf(m, __shfl_xor_sync(0xffffffffu, m, off, 4));
            if (t == 0)
                atomicMax(&g_rowmax[rr], fenc(m));
        }
    }
}

// ---------------------------------------------------------------------------
// Rescore: vectorized gather + warp-parallel exact sequential-fmaf dots.
// ---------------------------------------------------------------------------
__global__ void __launch_bounds__(256) rescore_kernel(float* __restrict__ out,
                                                      int N, int V) {
    int row = blockIdx.x;
    int tid = threadIdx.x;
    int wid = tid >> 5, lane = tid & 31;
    const uint4* crow = (const uint4*)(g_cosb + (size_t)row * V);  // 8 bf16 each

    __shared__ int   s_cnt;
    __shared__ int   s_cand[MAXCAND];
    __shared__ __align__(16) float s_z[KDIM];
    __shared__ __align__(16) float s_ew[8][KDIM];
    __shared__ float s_bv[8];
    __shared__ int   s_bc[8];

    s_z[tid] = g_znf[(size_t)row * KDIM + tid];
    if (tid == 0) s_cnt = 0;
    __syncthreads();

    float thr = fdec(g_rowmax[row]) - MARGIN;

    uint4 w0 = crow[tid];
    uint4 w1 = crow[tid + 256];
    #pragma unroll
    for (int half = 0; half < 2; half++) {
        uint4 w = half ? w1 : w0;
        unsigned u[4] = {w.x, w.y, w.z, w.w};
        int cbase = (tid + half * 256) * 8;
        #pragma unroll
        for (int j = 0; j < 4; j++) {
            float v0 = __uint_as_float(u[j] << 16);
            float v1 = __uint_as_float(u[j] & 0xFFFF0000u);
            if (v0 >= thr) {
                int pos = atomicAdd(&s_cnt, 1);
                if (pos < MAXCAND) s_cand[pos] = cbase + 2 * j;
            }
            if (v1 >= thr) {
                int pos = atomicAdd(&s_cnt, 1);
                if (pos < MAXCAND) s_cand[pos] = cbase + 2 * j + 1;
            }
        }
    }
    __syncthreads();
    int nc = min(s_cnt, MAXCAND);

    float bv = -4.0f;
    int   bc = 0x7fffffff;
    for (int i = wid; i < nc; i += 8) {
        int c = s_cand[i];
        const float4* e = (const float4*)(g_enf + (size_t)c * KDIM);
        ((float4*)s_ew[wid])[lane]      = e[lane];
        ((float4*)s_ew[wid])[lane + 32] = e[lane + 32];
        __syncwarp();
        if (lane == 0) {
            float d = 0.f;
            #pragma unroll 8
            for (int k = 0; k < KDIM; k++) d = fmaf(s_z[k], s_ew[wid][k], d);
            if (d > bv || (d == bv && c < bc)) { bv = d; bc = c; }
        }
        __syncwarp();
    }
    if (lane == 0) { s_bv[wid] = bv; s_bc[wid] = bc; }
    __syncthreads();

    if (tid == 0) {
        float fbv = -4.0f;
        int   fbc = 0x7fffffff;
        #pragma unroll
        for (int w = 0; w < 8; w++) {
            float d = s_bv[w];
            int   c = s_bc[w];
            if (d > fbv || (d == fbv && c < fbc)) { fbv = d; fbc = c; }
        }
        out[(size_t)N * (size_t)N + row] = (float)fbc;
    }
}

// ---------------------------------------------------------------------------
// Launch: adj concurrent with (cos -> rescore).
//   main: prep -> [evPrep] -> adj -> wait(evSide)
//   side: wait(evPrep) -> cos -> rescore -> [evSide]
// Streams/events created per call (capture-legal; no device memory).
// ---------------------------------------------------------------------------
extern "C" void kernel_launch(void* const* d_in, const int* in_sizes, int n_in,
                              void* d_out, int out_size) {
    const float* z = (const float*)d_in[0];
    const float* e = (const float*)d_in[1];
    float* out = (float*)d_out;

    int N = in_sizes[0] / KDIM;   // 8192
    int V = in_sizes[1] / KDIM;   // 4096
    int T = N / TILE;             // 64

    cudaFuncSetAttribute(adj_sym_kernel,
                         cudaFuncAttributeMaxDynamicSharedMemorySize, ADJ_SMEM);

    cudaStream_t side;
    cudaStreamCreateWithFlags(&side, cudaStreamNonBlocking);
    cudaEvent_t evPrep, evSide;
    cudaEventCreateWithFlags(&evPrep, cudaEventDisableTiming);
    cudaEventCreateWithFlags(&evSide, cudaEventDisableTiming);

    prep_kernel<<<N + V, 256>>>(z, e, N, V);
    cudaEventRecord(evPrep, 0);

    cudaStreamWaitEvent(side, evPrep, 0);
    dim3 gCos(V / TILE, N / TILE);
    cos_kernel<<<gCos, 256, 0, side>>>(N, V);
    rescore_kernel<<<N, 256, 0, side>>>(out, N, V);
    cudaEventRecord(evSide, side);

    int nTiles = T * (T + 1) / 2; // 2080
    adj_sym_kernel<<<nTiles, 256, ADJ_SMEM>>>(out, N);

    cudaStreamWaitEvent(0, evSide, 0);
}